// round 1
// baseline (speedup 1.0000x reference)
#include <cuda_runtime.h>
#include <math.h>

#define PI_F 3.14159265358979323846f
#define N_NODES 4096
#define N_EDGES 12288
#define NUM_GRAPHS 16

// ---------------- device scratch (no allocation allowed) ----------------
__device__ float  g_x[N_NODES * 2];
__device__ float  g_e[N_EDGES * 2];
__device__ float  g_aggr[N_NODES];
__device__ float2 g_gates[52];          // 13 complex 2x2 matrices
__device__ float  g_gsum[NUM_GRAPHS * 2];
__device__ float  g_gcnt[NUM_GRAPHS];

// ---------------- complex helpers ----------------
__device__ __forceinline__ float2 cmul(float2 a, float2 b) {
    return make_float2(a.x * b.x - a.y * b.y, a.x * b.y + a.y * b.x);
}
__device__ __forceinline__ float2 cadd(float2 a, float2 b) {
    return make_float2(a.x + b.x, a.y + b.y);
}
__device__ __forceinline__ unsigned ins_bit(unsigned x, int b) {
    return ((x >> b) << (b + 1)) | (x & ((1u << b) - 1u));
}

// ---------------- K0: precompute gate matrices + zero accumulators ----------------
__device__ void make_rot(const float* w, float2* m) {
    // Rot(phi,theta,omega) = Rz(omega) Ry(theta) Rz(phi)
    float phi = w[0], th = w[1], om = w[2];
    float c, s; sincosf(th * 0.5f, &s, &c);
    float sa, ca, sb, cb;
    sincosf((phi + om) * 0.5f, &sa, &ca);
    sincosf((phi - om) * 0.5f, &sb, &cb);
    m[0] = make_float2(c * ca, -c * sa);   // u00 = c e^{-i(phi+om)/2}
    m[1] = make_float2(-s * cb, -s * sb);  // u01 = -s e^{i(phi-om)/2}
    m[2] = make_float2(s * cb, -s * sb);   // u10 = s e^{-i(phi-om)/2}
    m[3] = make_float2(c * ca, c * sa);    // u11 = c e^{i(phi+om)/2}
}

__global__ void prep_kernel(const float* __restrict__ strong,
                            const float* __restrict__ inits,
                            const float* __restrict__ update) {
    int t = threadIdx.x;
    if (t < NUM_GRAPHS) {
        g_gsum[2 * t] = 0.f; g_gsum[2 * t + 1] = 0.f; g_gcnt[t] = 0.f;
    }
    if (t == 0) {
        float c, s;
        // target matrices of the 4 controlled gates: RX(i0), RY(i1), RZ(i2), RY(i3)
        sincosf(inits[0] * 0.5f, &s, &c);
        g_gates[0] = make_float2(c, 0); g_gates[1] = make_float2(0, -s);
        g_gates[2] = make_float2(0, -s); g_gates[3] = make_float2(c, 0);
        sincosf(inits[1] * 0.5f, &s, &c);
        g_gates[4] = make_float2(c, 0); g_gates[5] = make_float2(-s, 0);
        g_gates[6] = make_float2(s, 0); g_gates[7] = make_float2(c, 0);
        sincosf(inits[2] * 0.5f, &s, &c);
        g_gates[8]  = make_float2(c, -s); g_gates[9]  = make_float2(0, 0);
        g_gates[10] = make_float2(0, 0);  g_gates[11] = make_float2(c, s);
        sincosf(inits[3] * 0.5f, &s, &c);
        g_gates[12] = make_float2(c, 0); g_gates[13] = make_float2(-s, 0);
        g_gates[14] = make_float2(s, 0); g_gates[15] = make_float2(c, 0);
        // 9 Rot matrices: strong[0,0,j,:], strong[1,0,j,:], update[0,j,:]
        for (int j = 0; j < 3; j++) make_rot(strong + j * 3,      &g_gates[(4 + j) * 4]);
        for (int j = 0; j < 3; j++) make_rot(strong + 9 + j * 3,  &g_gates[(7 + j) * 4]);
        for (int j = 0; j < 3; j++) make_rot(update + j * 3,      &g_gates[(10 + j) * 4]);
    }
}

// ---------------- K1/K2: generic 2-layer MLP (NI -> 128 -> 2) ----------------
template <int NI, bool DO_TANH>
__global__ void mlp_kernel(const float* __restrict__ inp, int rows,
                           const float* __restrict__ W1, const float* __restrict__ b1,
                           const float* __restrict__ W2, const float* __restrict__ b2,
                           float* __restrict__ out) {
    __shared__ float sW1[NI * 128];
    __shared__ float sb1[128];
    __shared__ float sW2[256];
    __shared__ float sb2[2];
    for (int k = threadIdx.x; k < NI * 128; k += blockDim.x) sW1[k] = W1[k];
    for (int k = threadIdx.x; k < 128; k += blockDim.x) sb1[k] = b1[k];
    for (int k = threadIdx.x; k < 256; k += blockDim.x) sW2[k] = W2[k];
    if (threadIdx.x < 2) sb2[threadIdx.x] = b2[threadIdx.x];
    __syncthreads();
    int r = blockIdx.x * blockDim.x + threadIdx.x;
    if (r >= rows) return;
    float in[NI];
#pragma unroll
    for (int i = 0; i < NI; i++) in[i] = inp[r * NI + i];
    float o0 = sb2[0], o1 = sb2[1];
#pragma unroll 4
    for (int h = 0; h < 128; h++) {
        float a = sb1[h];
#pragma unroll
        for (int i = 0; i < NI; i++) a = fmaf(in[i], sW1[i * 128 + h], a);
        a = a > 0.f ? a : 0.01f * a;      // leaky_relu
        o0 = fmaf(a, sW2[2 * h], o0);
        o1 = fmaf(a, sW2[2 * h + 1], o1);
    }
    if (DO_TANH) { o0 = tanhf(o0) * PI_F; o1 = tanhf(o1) * PI_F; }
    out[2 * r] = o0; out[2 * r + 1] = o1;
}

// ---------------- K3: PQC statevector simulation, one state per block ----------------
// flat index bit for wire w is (8 - w)
__device__ __forceinline__ void apply1(float2* st, const float2* U, int b, int tid) {
    unsigned i0 = ins_bit((unsigned)tid, b);
    unsigned i1 = i0 | (1u << b);
    float2 s0 = st[i0], s1 = st[i1];
    st[i0] = cadd(cmul(U[0], s0), cmul(U[1], s1));
    st[i1] = cadd(cmul(U[2], s0), cmul(U[3], s1));
}
__device__ __forceinline__ void ctrl1(float2* st, const float2* U, int bc, int bt, int tid) {
    if (tid < 128) {
        int blo = bc < bt ? bc : bt;
        int bhi = bc < bt ? bt : bc;
        unsigned t = ins_bit(ins_bit((unsigned)tid, blo), bhi);
        unsigned i0 = t | (1u << bc);         // control = 1, target = 0
        unsigned i1 = i0 | (1u << bt);        // control = 1, target = 1
        float2 s0 = st[i0], s1 = st[i1];
        st[i0] = cadd(cmul(U[0], s0), cmul(U[1], s1));
        st[i1] = cadd(cmul(U[2], s0), cmul(U[3], s1));
    }
}
__device__ __forceinline__ void cnotg(float2* st, int bc, int bt, int tid) {
    if (tid < 128) {
        int blo = bc < bt ? bc : bt;
        int bhi = bc < bt ? bt : bc;
        unsigned t = ins_bit(ins_bit((unsigned)tid, blo), bhi);
        unsigned i0 = t | (1u << bc);
        unsigned i1 = i0 | (1u << bt);
        float2 tmp = st[i0]; st[i0] = st[i1]; st[i1] = tmp;
    }
}

__global__ void pqc_kernel(const int* __restrict__ subgraphs,
                           const int* __restrict__ edge_ids) {
    __shared__ float2 st[512];
    __shared__ float2 sG[52];
    __shared__ float2 tab[7][2];
    __shared__ float red[8];
    int tid = threadIdx.x;
    int s = blockIdx.x;

    if (tid < 52) sG[tid] = g_gates[tid];
    if (tid < 7) {
        float ry, rz;
        if (tid < 3) {
            int eid = edge_ids[s * 3 + tid];
            ry = g_e[2 * eid]; rz = g_e[2 * eid + 1];
        } else {
            int nid = subgraphs[s * 4 + (tid - 3)];
            ry = g_x[2 * nid]; rz = g_x[2 * nid + 1];
        }
        float sy, cy, sz, cz;
        sincosf(ry * 0.5f, &sy, &cy);
        sincosf(rz * 0.5f, &sz, &cz);
        tab[tid][0] = make_float2(cy * cz, -cy * sz);  // |0> amp after RY,RZ
        tab[tid][1] = make_float2(sy * cz,  sy * sz);  // |1> amp
    }
    __syncthreads();

    // initial encoded state is a product state: build directly
#pragma unroll
    for (int k = 0; k < 2; k++) {
        unsigned idx = (unsigned)tid + k * 256u;
        float2 a;
        if (idx & 3u) {                    // ancilla wires 7,8 (bits 1,0) must be 0
            a = make_float2(0.f, 0.f);
        } else {
            a = make_float2(1.f, 0.f);
#pragma unroll
            for (int w = 0; w < 7; w++)
                a = cmul(a, tab[w][(idx >> (8 - w)) & 1u]);
        }
        st[idx] = a;
    }
    __syncthreads();

#pragma unroll 1
    for (int i = 0; i < 3; i++) {
        int be = 8 - i;      // wire e = i
        int bnb = 4 - i;     // wire nb = 4+i
        // controlled gates: CRX(nb,a1) CRY(e,a1) CRZ(nb,a2) CRY(e,a2)
        ctrl1(st, &sG[0],  bnb, 1, tid); __syncthreads();
        ctrl1(st, &sG[4],  be,  1, tid); __syncthreads();
        ctrl1(st, &sG[8],  bnb, 0, tid); __syncthreads();
        ctrl1(st, &sG[12], be,  0, tid); __syncthreads();
        // sel(strong[0], [e, nb, a1])
        apply1(st, &sG[16], be,  tid); __syncthreads();
        apply1(st, &sG[20], bnb, tid); __syncthreads();
        apply1(st, &sG[24], 1,   tid); __syncthreads();
        cnotg(st, be, bnb, tid); __syncthreads();
        cnotg(st, bnb, 1,  tid); __syncthreads();
        cnotg(st, 1, be,   tid); __syncthreads();
        // sel(strong[1], [a1, nb, a2])
        apply1(st, &sG[28], 1,   tid); __syncthreads();
        apply1(st, &sG[32], bnb, tid); __syncthreads();
        apply1(st, &sG[36], 0,   tid); __syncthreads();
        cnotg(st, 1, bnb, tid); __syncthreads();
        cnotg(st, bnb, 0, tid); __syncthreads();
        cnotg(st, 0, 1,   tid); __syncthreads();
    }
    // final sel(update, [3, 7, 8])  -> bits 5, 1, 0
    apply1(st, &sG[40], 5, tid); __syncthreads();
    apply1(st, &sG[44], 1, tid); __syncthreads();
    apply1(st, &sG[48], 0, tid); __syncthreads();
    cnotg(st, 5, 1, tid); __syncthreads();
    cnotg(st, 1, 0, tid); __syncthreads();
    cnotg(st, 0, 5, tid); __syncthreads();

    // expectation: 2 * sum Re( conj(st[bit5=0]) * st[bit5=1] )
    unsigned i0 = ((tid >> 5) << 6) | (tid & 31u);
    float2 s0 = st[i0], s1 = st[i0 | 32u];
    float part = s0.x * s1.x + s0.y * s1.y;
#pragma unroll
    for (int o = 16; o; o >>= 1) part += __shfl_xor_sync(0xFFFFFFFFu, part, o);
    if ((tid & 31) == 0) red[tid >> 5] = part;
    __syncthreads();
    if (tid == 0) {
        float t = 0.f;
#pragma unroll
        for (int w = 0; w < 8; w++) t += red[w];
        g_aggr[s] = 2.0f * t;
    }
}

// ---------------- K4: update-MLP + fused segment sums ----------------
// gsum[g] = sum_{n in g} x[n]  +  sum_{rows r: batch[center_r]==g} upd_r
__global__ void upd_kernel(const int* __restrict__ subgraphs,
                           const int* __restrict__ batch,
                           const float* __restrict__ W1, const float* __restrict__ b1,
                           const float* __restrict__ W2, const float* __restrict__ b2) {
    __shared__ float sW1[3 * 128];
    __shared__ float sb1[128];
    __shared__ float sW2[256];
    __shared__ float sb2[2];
    __shared__ float sAcc[NUM_GRAPHS * 3];  // gs0, gs1, cnt
    int tid = threadIdx.x;
    for (int k = tid; k < 384; k += blockDim.x) sW1[k] = W1[k];
    for (int k = tid; k < 128; k += blockDim.x) sb1[k] = b1[k];
    for (int k = tid; k < 256; k += blockDim.x) sW2[k] = W2[k];
    if (tid < 2) sb2[tid] = b2[tid];
    if (tid < NUM_GRAPHS * 3) sAcc[tid] = 0.f;
    __syncthreads();

    int r = blockIdx.x * blockDim.x + tid;
    if (r < N_NODES) {
        int center = subgraphs[4 * r];
        float in0 = g_x[2 * center], in1 = g_x[2 * center + 1], in2 = g_aggr[r];
        float o0 = sb2[0], o1 = sb2[1];
#pragma unroll 4
        for (int h = 0; h < 128; h++) {
            float a = fmaf(in0, sW1[h],
                      fmaf(in1, sW1[128 + h],
                      fmaf(in2, sW1[256 + h], sb1[h])));
            a = a > 0.f ? a : 0.01f * a;
            o0 = fmaf(a, sW2[2 * h], o0);
            o1 = fmaf(a, sW2[2 * h + 1], o1);
        }
        int gu = batch[center];
        int gx = batch[r];
        atomicAdd(&sAcc[3 * gu + 0], o0);
        atomicAdd(&sAcc[3 * gu + 1], o1);
        atomicAdd(&sAcc[3 * gx + 0], g_x[2 * r]);
        atomicAdd(&sAcc[3 * gx + 1], g_x[2 * r + 1]);
        atomicAdd(&sAcc[3 * gx + 2], 1.f);
    }
    __syncthreads();
    if (tid < NUM_GRAPHS) {
        atomicAdd(&g_gsum[2 * tid],     sAcc[3 * tid + 0]);
        atomicAdd(&g_gsum[2 * tid + 1], sAcc[3 * tid + 1]);
        atomicAdd(&g_gcnt[tid],         sAcc[3 * tid + 2]);
    }
}

// ---------------- K5: head MLP (2 -> 2 -> 2) ----------------
__global__ void head_kernel(const float* __restrict__ Wh1, const float* __restrict__ bh1,
                            const float* __restrict__ Wh2, const float* __restrict__ bh2,
                            float* __restrict__ out) {
    int g = threadIdx.x;
    if (g >= NUM_GRAPHS) return;
    float cnt = g_gcnt[g];
    float g0 = g_gsum[2 * g] / cnt;
    float g1 = g_gsum[2 * g + 1] / cnt;
    float h0 = g0 * Wh1[0] + g1 * Wh1[2] + bh1[0];
    float h1 = g0 * Wh1[1] + g1 * Wh1[3] + bh1[1];
    h0 = h0 > 0.f ? h0 : 0.01f * h0;
    h1 = h1 > 0.f ? h1 : 0.01f * h1;
    out[2 * g]     = h0 * Wh2[0] + h1 * Wh2[2] + bh2[0];
    out[2 * g + 1] = h0 * Wh2[1] + h1 * Wh2[3] + bh2[1];
}

// ---------------- launch ----------------
extern "C" void kernel_launch(void* const* d_in, const int* in_sizes, int n_in,
                              void* d_out, int out_size) {
    const float* node_feat = (const float*)d_in[0];
    const float* edge_attr = (const float*)d_in[1];
    const float* Wn1 = (const float*)d_in[2];
    const float* bn1 = (const float*)d_in[3];
    const float* Wn2 = (const float*)d_in[4];
    const float* bn2 = (const float*)d_in[5];
    const float* We1 = (const float*)d_in[6];
    const float* be1 = (const float*)d_in[7];
    const float* We2 = (const float*)d_in[8];
    const float* be2 = (const float*)d_in[9];
    const float* strong = (const float*)d_in[10];
    const float* inits  = (const float*)d_in[11];
    const float* update = (const float*)d_in[12];
    const float* Wu1 = (const float*)d_in[13];
    const float* bu1 = (const float*)d_in[14];
    const float* Wu2 = (const float*)d_in[15];
    const float* bu2 = (const float*)d_in[16];
    const float* Wh1 = (const float*)d_in[17];
    const float* bh1 = (const float*)d_in[18];
    const float* Wh2 = (const float*)d_in[19];
    const float* bh2 = (const float*)d_in[20];
    const int* subgraphs = (const int*)d_in[21];
    const int* edge_ids  = (const int*)d_in[22];
    const int* batch     = (const int*)d_in[23];
    float* out = (float*)d_out;

    float *px, *pe;
    cudaGetSymbolAddress((void**)&px, g_x);
    cudaGetSymbolAddress((void**)&pe, g_e);

    prep_kernel<<<1, 64>>>(strong, inits, update);
    mlp_kernel<8, true><<<(N_NODES + 127) / 128, 128>>>(node_feat, N_NODES, Wn1, bn1, Wn2, bn2, px);
    mlp_kernel<4, true><<<(N_EDGES + 127) / 128, 128>>>(edge_attr, N_EDGES, We1, be1, We2, be2, pe);
    pqc_kernel<<<N_NODES, 256>>>(subgraphs, edge_ids);
    upd_kernel<<<N_NODES / 256, 256>>>(subgraphs, batch, Wu1, bu1, Wu2, bu2);
    head_kernel<<<1, 32>>>(Wh1, bh1, Wh2, bh2, out);
}

// round 2
// speedup vs baseline: 1.7607x; 1.7607x over previous
#include <cuda_runtime.h>
#include <math.h>

#define PI_F 3.14159265358979323846f
#define N_NODES 4096
#define N_EDGES 12288
#define NUM_GRAPHS 16

// ---------------- device scratch ----------------
__device__ float  g_x[N_NODES * 2];
__device__ float  g_e[N_EDGES * 2];
__device__ float  g_aggr[N_NODES];
__device__ float2 g_gates[52];          // 13 complex 2x2 matrices
__device__ float  g_gsum[NUM_GRAPHS * 2];
__device__ float  g_gcnt[NUM_GRAPHS];

// ---------------- complex helpers ----------------
__device__ __forceinline__ float2 cmul(float2 a, float2 b) {
    return make_float2(fmaf(a.x, b.x, -(a.y * b.y)), fmaf(a.x, b.y, a.y * b.x));
}
__device__ __forceinline__ float2 cfma(float2 a, float2 b, float2 c) {   // a*b + c
    return make_float2(fmaf(a.x, b.x, fmaf(-a.y, b.y, c.x)),
                       fmaf(a.x, b.y, fmaf( a.y, b.x, c.y)));
}
__device__ __forceinline__ float2 cadd(float2 a, float2 b) {
    return make_float2(a.x + b.x, a.y + b.y);
}

// ---------------- gate precompute (runs in block 0 of fused MLP kernel) ----------------
__device__ void make_rot(const float* w, float2* m) {
    float phi = w[0], th = w[1], om = w[2];
    float c, s; sincosf(th * 0.5f, &s, &c);
    float sa, ca, sb, cb;
    sincosf((phi + om) * 0.5f, &sa, &ca);
    sincosf((phi - om) * 0.5f, &sb, &cb);
    m[0] = make_float2(c * ca, -c * sa);
    m[1] = make_float2(-s * cb, -s * sb);
    m[2] = make_float2(s * cb, -s * sb);
    m[3] = make_float2(c * ca, c * sa);
}

__device__ void prep_gates(const float* strong, const float* inits, const float* update) {
    float c, s;
    sincosf(inits[0] * 0.5f, &s, &c);   // RX target
    g_gates[0] = make_float2(c, 0); g_gates[1] = make_float2(0, -s);
    g_gates[2] = make_float2(0, -s); g_gates[3] = make_float2(c, 0);
    sincosf(inits[1] * 0.5f, &s, &c);   // RY
    g_gates[4] = make_float2(c, 0); g_gates[5] = make_float2(-s, 0);
    g_gates[6] = make_float2(s, 0); g_gates[7] = make_float2(c, 0);
    sincosf(inits[2] * 0.5f, &s, &c);   // RZ
    g_gates[8]  = make_float2(c, -s); g_gates[9]  = make_float2(0, 0);
    g_gates[10] = make_float2(0, 0);  g_gates[11] = make_float2(c, s);
    sincosf(inits[3] * 0.5f, &s, &c);   // RY
    g_gates[12] = make_float2(c, 0); g_gates[13] = make_float2(-s, 0);
    g_gates[14] = make_float2(s, 0); g_gates[15] = make_float2(c, 0);
    for (int j = 0; j < 3; j++) make_rot(strong + j * 3,     &g_gates[(4 + j) * 4]);
    for (int j = 0; j < 3; j++) make_rot(strong + 9 + j * 3, &g_gates[(7 + j) * 4]);
    for (int j = 0; j < 3; j++) make_rot(update + j * 3,     &g_gates[(10 + j) * 4]);
}

// ---------------- fused node+edge MLP (+ prep) ----------------
template <int NI>
__device__ __forceinline__ void mlp_row(const float* __restrict__ inp, int r,
                                        const float* sW1, const float* sb1,
                                        const float* sW2, const float* sb2,
                                        float* __restrict__ outp) {
    float in[NI];
#pragma unroll
    for (int i = 0; i < NI; i++) in[i] = inp[r * NI + i];
    float o0 = sb2[0], o1 = sb2[1];
#pragma unroll 4
    for (int h = 0; h < 128; h++) {
        float a = sb1[h];
#pragma unroll
        for (int i = 0; i < NI; i++) a = fmaf(in[i], sW1[i * 128 + h], a);
        a = a > 0.f ? a : 0.01f * a;
        o0 = fmaf(a, sW2[2 * h], o0);
        o1 = fmaf(a, sW2[2 * h + 1], o1);
    }
    outp[2 * r]     = tanhf(o0) * PI_F;
    outp[2 * r + 1] = tanhf(o1) * PI_F;
}

__global__ void __launch_bounds__(256) mlp_fused_kernel(
    const float* __restrict__ node_feat,
    const float* __restrict__ Wn1, const float* __restrict__ bn1,
    const float* __restrict__ Wn2, const float* __restrict__ bn2,
    const float* __restrict__ edge_attr,
    const float* __restrict__ We1, const float* __restrict__ be1,
    const float* __restrict__ We2, const float* __restrict__ be2,
    const float* __restrict__ strong, const float* __restrict__ inits,
    const float* __restrict__ update) {
    __shared__ float sW1[8 * 128];
    __shared__ float sb1[128];
    __shared__ float sW2[256];
    __shared__ float sb2[2];
    int b = blockIdx.x, tid = threadIdx.x;
    bool isNode = (b < 16);
    const float* W1 = isNode ? Wn1 : We1;
    const float* b1 = isNode ? bn1 : be1;
    const float* W2 = isNode ? Wn2 : We2;
    const float* b2 = isNode ? bn2 : be2;
    int ni = isNode ? 8 : 4;
    for (int k = tid; k < ni * 128; k += 256) sW1[k] = W1[k];
    for (int k = tid; k < 128; k += 256) sb1[k] = b1[k];
    for (int k = tid; k < 256; k += 256) sW2[k] = W2[k];
    if (tid < 2) sb2[tid] = b2[tid];

    if (b == 0) {   // prep: zero accumulators + compute gate matrices
        if (tid < NUM_GRAPHS) {
            g_gsum[2 * tid] = 0.f; g_gsum[2 * tid + 1] = 0.f; g_gcnt[tid] = 0.f;
        }
        if (tid == 32) prep_gates(strong, inits, update);
    }
    __syncthreads();

    if (isNode)
        mlp_row<8>(node_feat, b * 256 + tid, sW1, sb1, sW2, sb2, g_x);
    else
        mlp_row<4>(edge_attr, (b - 16) * 256 + tid, sW1, sb1, sW2, sb2, g_e);
}

// ================= PQC: warp-per-state, register-resident =================
// index bit -> storage:  bit0->R0 bit1->R1 bit4->R2 bit5->R3 (register bits of r)
//                        bit2->L0 bit3->L1 bit6->L2 bit7->L3 bit8->L4 (lane bits)

// 1q gate on register bit J
template <int J>
__device__ __forceinline__ void ap_reg(float2* v, const float2* U) {
    float2 u0 = U[0], u1 = U[1], u2 = U[2], u3 = U[3];
#pragma unroll
    for (int r = 0; r < 16; r++) {
        if ((r >> J) & 1) continue;
        int r2 = r | (1 << J);
        float2 a = v[r], b = v[r2];
        v[r]  = cfma(u1, b, cmul(u0, a));
        v[r2] = cfma(u3, b, cmul(u2, a));
    }
}
// 1q gate on lane bit (runtime mask)
__device__ __forceinline__ void ap_lane(float2* v, const float2* U, int lane, int mask) {
    bool bit = lane & mask;
    float2 A = bit ? U[3] : U[0];
    float2 B = bit ? U[2] : U[1];
#pragma unroll
    for (int r = 0; r < 16; r++) {
        float2 o;
        o.x = __shfl_xor_sync(0xffffffffu, v[r].x, mask);
        o.y = __shfl_xor_sync(0xffffffffu, v[r].y, mask);
        v[r] = cfma(B, o, cmul(A, v[r]));
    }
}
// controlled 1q: control reg bit C, target reg bit T
template <int C, int T>
__device__ __forceinline__ void ctrl_rr(float2* v, const float2* U) {
    float2 u0 = U[0], u1 = U[1], u2 = U[2], u3 = U[3];
#pragma unroll
    for (int r = 0; r < 16; r++) {
        if (!((r >> C) & 1) || ((r >> T) & 1)) continue;
        int r2 = r | (1 << T);
        float2 a = v[r], b = v[r2];
        v[r]  = cfma(u1, b, cmul(u0, a));
        v[r2] = cfma(u3, b, cmul(u2, a));
    }
}
// controlled 1q: control lane bit (runtime mask), target reg bit T
template <int T>
__device__ __forceinline__ void ctrl_lr(float2* v, const float2* U, int lane, int cmask) {
    if (lane & cmask) {
        float2 u0 = U[0], u1 = U[1], u2 = U[2], u3 = U[3];
#pragma unroll
        for (int r = 0; r < 16; r++) {
            if ((r >> T) & 1) continue;
            int r2 = r | (1 << T);
            float2 a = v[r], b = v[r2];
            v[r]  = cfma(u1, b, cmul(u0, a));
            v[r2] = cfma(u3, b, cmul(u2, a));
        }
    }
}
// CNOT: control reg C, target reg T
template <int C, int T>
__device__ __forceinline__ void cnot_rr(float2* v) {
#pragma unroll
    for (int r = 0; r < 16; r++) {
        if (!((r >> C) & 1) || ((r >> T) & 1)) continue;
        int r2 = r | (1 << T);
        float2 t = v[r]; v[r] = v[r2]; v[r2] = t;
    }
}
// CNOT: control reg C, target lane bit (runtime mask) -- swap via shuffle
template <int C>
__device__ __forceinline__ void cnot_rl(float2* v, int tmask) {
#pragma unroll
    for (int r = 0; r < 16; r++) {
        if (!((r >> C) & 1)) continue;
        v[r].x = __shfl_xor_sync(0xffffffffu, v[r].x, tmask);
        v[r].y = __shfl_xor_sync(0xffffffffu, v[r].y, tmask);
    }
}
// CNOT: control lane bit, target reg bit T
template <int T>
__device__ __forceinline__ void cnot_lr(float2* v, int lane, int cmask) {
    if (lane & cmask) {
#pragma unroll
        for (int r = 0; r < 16; r++) {
            if ((r >> T) & 1) continue;
            int r2 = r | (1 << T);
            float2 t = v[r]; v[r] = v[r2]; v[r2] = t;
        }
    }
}
// CNOT: control lane bit, target lane bit
__device__ __forceinline__ void cnot_ll(float2* v, int lane, int cmask, int tmask) {
    bool c = lane & cmask;
#pragma unroll
    for (int r = 0; r < 16; r++) {
        float2 o;
        o.x = __shfl_xor_sync(0xffffffffu, v[r].x, tmask);
        o.y = __shfl_xor_sync(0xffffffffu, v[r].y, tmask);
        if (c) v[r] = o;
    }
}

__device__ __forceinline__ float2 wire_factor(float ry, float rz, int bit) {
    float sy, cy, sz, cz;
    sincosf(0.5f * ry, &sy, &cy);
    sincosf(0.5f * rz, &sz, &cz);
    return bit ? make_float2(sy * cz, sy * sz) : make_float2(cy * cz, -cy * sz);
}

__global__ void __launch_bounds__(256) pqc_kernel(const int* __restrict__ subgraphs,
                                                  const int* __restrict__ edge_ids) {
    __shared__ float2 sG[52];
    int tid = threadIdx.x;
    if (tid < 52) sG[tid] = g_gates[tid];
    __syncthreads();
    int lane = tid & 31;
    int s = blockIdx.x * 8 + (tid >> 5);

    // ---- initial product state ----
    // wires 0..2 = edges (bits 8,7,6 -> L4,L3,L2); wire3 (bit5->R3), wire4 (bit4->R2),
    // wire5 (bit3->L1), wire6 (bit2->L0); ancillas bits1,0 -> R1,R0 = 0
    int e0 = edge_ids[3 * s], e1 = edge_ids[3 * s + 1], e2 = edge_ids[3 * s + 2];
    int n0 = subgraphs[4 * s], n1 = subgraphs[4 * s + 1],
        n2 = subgraphs[4 * s + 2], n3 = subgraphs[4 * s + 3];

    float2 lf = wire_factor(g_e[2 * e0], g_e[2 * e0 + 1], (lane >> 4) & 1);
    lf = cmul(lf, wire_factor(g_e[2 * e1], g_e[2 * e1 + 1], (lane >> 3) & 1));
    lf = cmul(lf, wire_factor(g_e[2 * e2], g_e[2 * e2 + 1], (lane >> 2) & 1));
    lf = cmul(lf, wire_factor(g_x[2 * n2], g_x[2 * n2 + 1], (lane >> 1) & 1));   // wire5
    lf = cmul(lf, wire_factor(g_x[2 * n3], g_x[2 * n3 + 1], lane & 1));          // wire6
    float2 f3_0 = wire_factor(g_x[2 * n0], g_x[2 * n0 + 1], 0);   // wire3 -> R3
    float2 f3_1 = wire_factor(g_x[2 * n0], g_x[2 * n0 + 1], 1);
    float2 f4_0 = wire_factor(g_x[2 * n1], g_x[2 * n1 + 1], 0);   // wire4 -> R2
    float2 f4_1 = wire_factor(g_x[2 * n1], g_x[2 * n1 + 1], 1);

    float2 v[16];
#pragma unroll
    for (int r = 0; r < 16; r++) v[r] = make_float2(0.f, 0.f);
    v[0]  = cmul(lf, cmul(f4_0, f3_0));
    v[4]  = cmul(lf, cmul(f4_1, f3_0));
    v[8]  = cmul(lf, cmul(f4_0, f3_1));
    v[12] = cmul(lf, cmul(f4_1, f3_1));

    // ---- iteration i=0: be = bit8 (L4, mask16), bnb = bit4 (R2) ----
    ctrl_rr<2, 1>(v, &sG[0]);
    ctrl_lr<1>(v, &sG[4], lane, 16);
    ctrl_rr<2, 0>(v, &sG[8]);
    ctrl_lr<0>(v, &sG[12], lane, 16);
    ap_lane(v, &sG[16], lane, 16);      // rot on e
    ap_reg<2>(v, &sG[20]);              // rot on nb
    ap_reg<1>(v, &sG[24]);              // rot on a1
    cnot_lr<2>(v, lane, 16);            // cnot(e, nb)
    cnot_rr<2, 1>(v);                   // cnot(nb, a1)
    cnot_rl<1>(v, 16);                  // cnot(a1, e)
    ap_reg<1>(v, &sG[28]);              // rot a1
    ap_reg<2>(v, &sG[32]);              // rot nb
    ap_reg<0>(v, &sG[36]);              // rot a2
    cnot_rr<1, 2>(v);                   // cnot(a1, nb)
    cnot_rr<2, 0>(v);                   // cnot(nb, a2)
    cnot_rr<0, 1>(v);                   // cnot(a2, a1)

    // ---- iterations i=1,2: be,bnb both lane bits ----
#pragma unroll 1
    for (int i = 1; i < 3; i++) {
        int emask = 1 << (4 - i);       // bit7->L3(8), bit6->L2(4)
        int nmask = 1 << (2 - i);       // bit3->L1(2), bit2->L0(1)
        ctrl_lr<1>(v, &sG[0], lane, nmask);
        ctrl_lr<1>(v, &sG[4], lane, emask);
        ctrl_lr<0>(v, &sG[8], lane, nmask);
        ctrl_lr<0>(v, &sG[12], lane, emask);
        ap_lane(v, &sG[16], lane, emask);
        ap_lane(v, &sG[20], lane, nmask);
        ap_reg<1>(v, &sG[24]);
        cnot_ll(v, lane, emask, nmask);     // cnot(e, nb)
        cnot_lr<1>(v, lane, nmask);         // cnot(nb, a1)
        cnot_rl<1>(v, emask);               // cnot(a1, e)
        ap_reg<1>(v, &sG[28]);
        ap_lane(v, &sG[32], lane, nmask);
        ap_reg<0>(v, &sG[36]);
        cnot_rl<1>(v, nmask);               // cnot(a1, nb)
        cnot_lr<0>(v, lane, nmask);         // cnot(nb, a2)
        cnot_rr<0, 1>(v);                   // cnot(a2, a1)
    }

    // ---- final sel on wires 3,7,8 -> bits 5(R3), 1(R1), 0(R0) ----
    ap_reg<3>(v, &sG[40]);
    ap_reg<1>(v, &sG[44]);
    ap_reg<0>(v, &sG[48]);
    cnot_rr<3, 1>(v);
    cnot_rr<1, 0>(v);
    cnot_rr<0, 3>(v);

    // ---- expectation: 2 * Re sum conj(s[bit5=0]) * s[bit5=1]; bit5 = R3 ----
    float part = 0.f;
#pragma unroll
    for (int r = 0; r < 8; r++)
        part += v[r].x * v[r + 8].x + v[r].y * v[r + 8].y;
#pragma unroll
    for (int o = 16; o; o >>= 1) part += __shfl_xor_sync(0xffffffffu, part, o);
    if (lane == 0) g_aggr[s] = 2.0f * part;
}

// ---------------- K4: update-MLP + fused segment sums ----------------
__global__ void __launch_bounds__(256) upd_kernel(const int* __restrict__ subgraphs,
                           const int* __restrict__ batch,
                           const float* __restrict__ W1, const float* __restrict__ b1,
                           const float* __restrict__ W2, const float* __restrict__ b2) {
    __shared__ float sW1[3 * 128];
    __shared__ float sb1[128];
    __shared__ float sW2[256];
    __shared__ float sb2[2];
    __shared__ float sAcc[NUM_GRAPHS * 3];
    int tid = threadIdx.x;
    for (int k = tid; k < 384; k += 256) sW1[k] = W1[k];
    for (int k = tid; k < 128; k += 256) sb1[k] = b1[k];
    for (int k = tid; k < 256; k += 256) sW2[k] = W2[k];
    if (tid < 2) sb2[tid] = b2[tid];
    if (tid < NUM_GRAPHS * 3) sAcc[tid] = 0.f;
    __syncthreads();

    int r = blockIdx.x * 256 + tid;
    {
        int center = subgraphs[4 * r];
        float in0 = g_x[2 * center], in1 = g_x[2 * center + 1], in2 = g_aggr[r];
        float o0 = sb2[0], o1 = sb2[1];
#pragma unroll 4
        for (int h = 0; h < 128; h++) {
            float a = fmaf(in0, sW1[h],
                      fmaf(in1, sW1[128 + h],
                      fmaf(in2, sW1[256 + h], sb1[h])));
            a = a > 0.f ? a : 0.01f * a;
            o0 = fmaf(a, sW2[2 * h], o0);
            o1 = fmaf(a, sW2[2 * h + 1], o1);
        }
        int gu = batch[center];
        int gx = batch[r];
        atomicAdd(&sAcc[3 * gu + 0], o0);
        atomicAdd(&sAcc[3 * gu + 1], o1);
        atomicAdd(&sAcc[3 * gx + 0], g_x[2 * r]);
        atomicAdd(&sAcc[3 * gx + 1], g_x[2 * r + 1]);
        atomicAdd(&sAcc[3 * gx + 2], 1.f);
    }
    __syncthreads();
    if (tid < NUM_GRAPHS) {
        atomicAdd(&g_gsum[2 * tid],     sAcc[3 * tid + 0]);
        atomicAdd(&g_gsum[2 * tid + 1], sAcc[3 * tid + 1]);
        atomicAdd(&g_gcnt[tid],         sAcc[3 * tid + 2]);
    }
}

// ---------------- K5: head MLP ----------------
__global__ void head_kernel(const float* __restrict__ Wh1, const float* __restrict__ bh1,
                            const float* __restrict__ Wh2, const float* __restrict__ bh2,
                            float* __restrict__ out) {
    int g = threadIdx.x;
    if (g >= NUM_GRAPHS) return;
    float cnt = g_gcnt[g];
    float g0 = g_gsum[2 * g] / cnt;
    float g1 = g_gsum[2 * g + 1] / cnt;
    float h0 = g0 * Wh1[0] + g1 * Wh1[2] + bh1[0];
    float h1 = g0 * Wh1[1] + g1 * Wh1[3] + bh1[1];
    h0 = h0 > 0.f ? h0 : 0.01f * h0;
    h1 = h1 > 0.f ? h1 : 0.01f * h1;
    out[2 * g]     = h0 * Wh2[0] + h1 * Wh2[2] + bh2[0];
    out[2 * g + 1] = h0 * Wh2[1] + h1 * Wh2[3] + bh2[1];
}

// ---------------- launch ----------------
extern "C" void kernel_launch(void* const* d_in, const int* in_sizes, int n_in,
                              void* d_out, int out_size) {
    const float* node_feat = (const float*)d_in[0];
    const float* edge_attr = (const float*)d_in[1];
    const float* Wn1 = (const float*)d_in[2];
    const float* bn1 = (const float*)d_in[3];
    const float* Wn2 = (const float*)d_in[4];
    const float* bn2 = (const float*)d_in[5];
    const float* We1 = (const float*)d_in[6];
    const float* be1 = (const float*)d_in[7];
    const float* We2 = (const float*)d_in[8];
    const float* be2 = (const float*)d_in[9];
    const float* strong = (const float*)d_in[10];
    const float* inits  = (const float*)d_in[11];
    const float* update = (const float*)d_in[12];
    const float* Wu1 = (const float*)d_in[13];
    const float* bu1 = (const float*)d_in[14];
    const float* Wu2 = (const float*)d_in[15];
    const float* bu2 = (const float*)d_in[16];
    const float* Wh1 = (const float*)d_in[17];
    const float* bh1 = (const float*)d_in[18];
    const float* Wh2 = (const float*)d_in[19];
    const float* bh2 = (const float*)d_in[20];
    const int* subgraphs = (const int*)d_in[21];
    const int* edge_ids  = (const int*)d_in[22];
    const int* batch     = (const int*)d_in[23];
    float* out = (float*)d_out;

    mlp_fused_kernel<<<64, 256>>>(node_feat, Wn1, bn1, Wn2, bn2,
                                  edge_attr, We1, be1, We2, be2,
                                  strong, inits, update);
    pqc_kernel<<<512, 256>>>(subgraphs, edge_ids);
    upd_kernel<<<16, 256>>>(subgraphs, batch, Wu1, bu1, Wu2, bu2);
    head_kernel<<<1, 32>>>(Wh1, bh1, Wh2, bh2, out);
}

// round 3
// speedup vs baseline: 3.0403x; 1.7268x over previous
#include <cuda_runtime.h>
#include <math.h>

#define PI_F 3.14159265358979323846f
#define N_NODES 4096
#define N_EDGES 12288
#define NUM_GRAPHS 16
#define PQC_BLOCKS 512

// ---------------- device scratch ----------------
__device__ float  g_x[N_NODES * 2];
__device__ float  g_e[N_EDGES * 2];
__device__ float2 g_gates[52];   // [0..3]: (c,s) of CRX,CRY1,CRZ,CRY2 targets; [16..51]: 9 rot matrices
__device__ float  g_gsum[NUM_GRAPHS * 2];
__device__ float  g_gcnt[NUM_GRAPHS];
__device__ int    g_done;

// ---------------- complex helpers ----------------
__device__ __forceinline__ float2 cmul(float2 a, float2 b) {
    return make_float2(fmaf(a.x, b.x, -(a.y * b.y)), fmaf(a.x, b.y, a.y * b.x));
}
__device__ __forceinline__ float2 cfma(float2 a, float2 b, float2 c) {   // a*b + c
    return make_float2(fmaf(a.x, b.x, fmaf(-a.y, b.y, c.x)),
                       fmaf(a.x, b.y, fmaf( a.y, b.x, c.y)));
}

// ---------------- gate precompute ----------------
__device__ void make_rot(const float* w, float2* m) {
    float phi = w[0], th = w[1], om = w[2];
    float c, s; sincosf(th * 0.5f, &s, &c);
    float sa, ca, sb, cb;
    sincosf((phi + om) * 0.5f, &sa, &ca);
    sincosf((phi - om) * 0.5f, &sb, &cb);
    m[0] = make_float2(c * ca, -c * sa);
    m[1] = make_float2(-s * cb, -s * sb);
    m[2] = make_float2(s * cb, -s * sb);
    m[3] = make_float2(c * ca, c * sa);
}

__device__ void prep_gates(const float* strong, const float* inits, const float* update) {
    float c, s;
    sincosf(inits[0] * 0.5f, &s, &c); g_gates[0] = make_float2(c, s);  // CRX target
    sincosf(inits[1] * 0.5f, &s, &c); g_gates[1] = make_float2(c, s);  // CRY1
    sincosf(inits[2] * 0.5f, &s, &c); g_gates[2] = make_float2(c, s);  // CRZ
    sincosf(inits[3] * 0.5f, &s, &c); g_gates[3] = make_float2(c, s);  // CRY2
    for (int j = 0; j < 3; j++) make_rot(strong + j * 3,     &g_gates[(4 + j) * 4]);
    for (int j = 0; j < 3; j++) make_rot(strong + 9 + j * 3, &g_gates[(7 + j) * 4]);
    for (int j = 0; j < 3; j++) make_rot(update + j * 3,     &g_gates[(10 + j) * 4]);
}

// ---------------- fused node+edge MLP (+ prep) ----------------
template <int NI>
__device__ __forceinline__ void mlp_row(const float* __restrict__ inp, int r,
                                        const float* sW1, const float* sb1,
                                        const float* sW2, const float* sb2,
                                        float* __restrict__ outp) {
    float in[NI];
#pragma unroll
    for (int i = 0; i < NI; i++) in[i] = inp[r * NI + i];
    float o0 = sb2[0], o1 = sb2[1];
#pragma unroll 4
    for (int h = 0; h < 128; h++) {
        float a = sb1[h];
#pragma unroll
        for (int i = 0; i < NI; i++) a = fmaf(in[i], sW1[i * 128 + h], a);
        a = a > 0.f ? a : 0.01f * a;
        o0 = fmaf(a, sW2[2 * h], o0);
        o1 = fmaf(a, sW2[2 * h + 1], o1);
    }
    outp[2 * r]     = tanhf(o0) * PI_F;
    outp[2 * r + 1] = tanhf(o1) * PI_F;
}

__global__ void __launch_bounds__(256) mlp_fused_kernel(
    const float* __restrict__ node_feat,
    const float* __restrict__ Wn1, const float* __restrict__ bn1,
    const float* __restrict__ Wn2, const float* __restrict__ bn2,
    const float* __restrict__ edge_attr,
    const float* __restrict__ We1, const float* __restrict__ be1,
    const float* __restrict__ We2, const float* __restrict__ be2,
    const float* __restrict__ strong, const float* __restrict__ inits,
    const float* __restrict__ update) {
    __shared__ float sW1[8 * 128];
    __shared__ float sb1[128];
    __shared__ float sW2[256];
    __shared__ float sb2[2];
    int b = blockIdx.x, tid = threadIdx.x;
    bool isNode = (b < 16);
    const float* W1 = isNode ? Wn1 : We1;
    const float* b1 = isNode ? bn1 : be1;
    const float* W2 = isNode ? Wn2 : We2;
    const float* b2 = isNode ? bn2 : be2;
    int ni = isNode ? 8 : 4;
    for (int k = tid; k < ni * 128; k += 256) sW1[k] = W1[k];
    for (int k = tid; k < 128; k += 256) sb1[k] = b1[k];
    for (int k = tid; k < 256; k += 256) sW2[k] = W2[k];
    if (tid < 2) sb2[tid] = b2[tid];

    if (b == 0) {   // prep: zero accumulators + compute gate matrices
        if (tid < NUM_GRAPHS) {
            g_gsum[2 * tid] = 0.f; g_gsum[2 * tid + 1] = 0.f; g_gcnt[tid] = 0.f;
        }
        if (tid == 33) g_done = 0;
        if (tid == 32) prep_gates(strong, inits, update);
    }
    __syncthreads();

    if (isNode)
        mlp_row<8>(node_feat, b * 256 + tid, sW1, sb1, sW2, sb2, g_x);
    else
        mlp_row<4>(edge_attr, (b - 16) * 256 + tid, sW1, sb1, sW2, sb2, g_e);
}

// ================= PQC: warp-per-state, register-resident =================
// index bit -> storage: bit0->R0 bit1->R1 bit4->R2 bit5->R3 (register bits)
//                       bit2->L0 bit3->L1 bit6->L2 bit7->L3 bit8->L4 (lane bits)

// generic 1q gate on register bit J
template <int J>
__device__ __forceinline__ void ap_reg(float2* v, const float2* U) {
    float2 u0 = U[0], u1 = U[1], u2 = U[2], u3 = U[3];
#pragma unroll
    for (int r = 0; r < 16; r++) {
        if ((r >> J) & 1) continue;
        int r2 = r | (1 << J);
        float2 a = v[r], b = v[r2];
        v[r]  = cfma(u1, b, cmul(u0, a));
        v[r2] = cfma(u3, b, cmul(u2, a));
    }
}
// generic 1q gate on lane bit
__device__ __forceinline__ void ap_lane(float2* v, const float2* U, int lane, int mask) {
    bool bit = lane & mask;
    float2 A = bit ? U[3] : U[0];
    float2 B = bit ? U[2] : U[1];
#pragma unroll
    for (int r = 0; r < 16; r++) {
        float2 o;
        o.x = __shfl_xor_sync(0xffffffffu, v[r].x, mask);
        o.y = __shfl_xor_sync(0xffffffffu, v[r].y, mask);
        v[r] = cfma(B, o, cmul(A, v[r]));
    }
}
// ---- structured controlled gates ----
// CRX: target [[c,-is],[-is,c]]
template <int C, int T>
__device__ __forceinline__ void crx_rr(float2* v, float c, float s) {
#pragma unroll
    for (int r = 0; r < 16; r++) {
        if (!((r >> C) & 1) || ((r >> T) & 1)) continue;
        int r2 = r | (1 << T);
        float2 a = v[r], b = v[r2];
        v[r]  = make_float2(fmaf(c, a.x,  s * b.y), fmaf(c, a.y, -s * b.x));
        v[r2] = make_float2(fmaf(c, b.x,  s * a.y), fmaf(c, b.y, -s * a.x));
    }
}
template <int T>
__device__ __forceinline__ void crx_lr(float2* v, float c, float s, int lane, int cmask) {
    if (lane & cmask) {
#pragma unroll
        for (int r = 0; r < 16; r++) {
            if ((r >> T) & 1) continue;
            int r2 = r | (1 << T);
            float2 a = v[r], b = v[r2];
            v[r]  = make_float2(fmaf(c, a.x,  s * b.y), fmaf(c, a.y, -s * b.x));
            v[r2] = make_float2(fmaf(c, b.x,  s * a.y), fmaf(c, b.y, -s * a.x));
        }
    }
}
// CRY: target [[c,-s],[s,c]] (all real)
template <int C, int T>
__device__ __forceinline__ void cry_rr(float2* v, float c, float s) {
#pragma unroll
    for (int r = 0; r < 16; r++) {
        if (!((r >> C) & 1) || ((r >> T) & 1)) continue;
        int r2 = r | (1 << T);
        float2 a = v[r], b = v[r2];
        v[r]  = make_float2(fmaf(c, a.x, -s * b.x), fmaf(c, a.y, -s * b.y));
        v[r2] = make_float2(fmaf(c, b.x,  s * a.x), fmaf(c, b.y,  s * a.y));
    }
}
template <int T>
__device__ __forceinline__ void cry_lr(float2* v, float c, float s, int lane, int cmask) {
    if (lane & cmask) {
#pragma unroll
        for (int r = 0; r < 16; r++) {
            if ((r >> T) & 1) continue;
            int r2 = r | (1 << T);
            float2 a = v[r], b = v[r2];
            v[r]  = make_float2(fmaf(c, a.x, -s * b.x), fmaf(c, a.y, -s * b.y));
            v[r2] = make_float2(fmaf(c, b.x,  s * a.x), fmaf(c, b.y,  s * a.y));
        }
    }
}
// CRZ: target diag(e^{-is},e^{+is}) -> pure per-amp phase
template <int C, int T>
__device__ __forceinline__ void crz_rr(float2* v, float c, float s) {
#pragma unroll
    for (int r = 0; r < 16; r++) {
        if (!((r >> C) & 1)) continue;
        float sg = ((r >> T) & 1) ? -s : s;
        float2 a = v[r];
        v[r] = make_float2(fmaf(c, a.x, sg * a.y), fmaf(c, a.y, -sg * a.x));
    }
}
template <int T>
__device__ __forceinline__ void crz_lr(float2* v, float c, float s, int lane, int cmask) {
    if (lane & cmask) {
#pragma unroll
        for (int r = 0; r < 16; r++) {
            float sg = ((r >> T) & 1) ? -s : s;
            float2 a = v[r];
            v[r] = make_float2(fmaf(c, a.x, sg * a.y), fmaf(c, a.y, -sg * a.x));
        }
    }
}
// ---- CNOTs ----
template <int C, int T>
__device__ __forceinline__ void cnot_rr(float2* v) {
#pragma unroll
    for (int r = 0; r < 16; r++) {
        if (!((r >> C) & 1) || ((r >> T) & 1)) continue;
        int r2 = r | (1 << T);
        float2 t = v[r]; v[r] = v[r2]; v[r2] = t;
    }
}
template <int C>
__device__ __forceinline__ void cnot_rl(float2* v, int tmask) {
#pragma unroll
    for (int r = 0; r < 16; r++) {
        if (!((r >> C) & 1)) continue;
        v[r].x = __shfl_xor_sync(0xffffffffu, v[r].x, tmask);
        v[r].y = __shfl_xor_sync(0xffffffffu, v[r].y, tmask);
    }
}
template <int T>
__device__ __forceinline__ void cnot_lr(float2* v, int lane, int cmask) {
    if (lane & cmask) {
#pragma unroll
        for (int r = 0; r < 16; r++) {
            if ((r >> T) & 1) continue;
            int r2 = r | (1 << T);
            float2 t = v[r]; v[r] = v[r2]; v[r2] = t;
        }
    }
}
__device__ __forceinline__ void cnot_ll(float2* v, int lane, int cmask, int tmask) {
    bool c = lane & cmask;
#pragma unroll
    for (int r = 0; r < 16; r++) {
        float2 o;
        o.x = __shfl_xor_sync(0xffffffffu, v[r].x, tmask);
        o.y = __shfl_xor_sync(0xffffffffu, v[r].y, tmask);
        if (c) v[r] = o;
    }
}

__device__ __forceinline__ float2 wire_factor(float ry, float rz, int bit) {
    float sy, cy, sz, cz;
    sincosf(0.5f * ry, &sy, &cy);
    sincosf(0.5f * rz, &sz, &cz);
    return bit ? make_float2(sy * cz, sy * sz) : make_float2(cy * cz, -cy * sz);
}

// one sel+ctrl iteration, ctrl/e masks compile-time where possible
template <int EMASK, int NMASK>
__device__ __forceinline__ void iter_lane(float2* v, const float2* sG, const float2* sC, int lane) {
    crx_lr<1>(v, sC[0].x, sC[0].y, lane, NMASK);
    cry_lr<1>(v, sC[1].x, sC[1].y, lane, EMASK);
    crz_lr<0>(v, sC[2].x, sC[2].y, lane, NMASK);
    cry_lr<0>(v, sC[3].x, sC[3].y, lane, EMASK);
    ap_lane(v, &sG[16], lane, EMASK);
    ap_lane(v, &sG[20], lane, NMASK);
    ap_reg<1>(v, &sG[24]);
    cnot_ll(v, lane, EMASK, NMASK);
    cnot_lr<1>(v, lane, NMASK);
    cnot_rl<1>(v, EMASK);
    ap_reg<1>(v, &sG[28]);
    ap_lane(v, &sG[32], lane, NMASK);
    ap_reg<0>(v, &sG[36]);
    cnot_rl<1>(v, NMASK);
    cnot_lr<0>(v, lane, NMASK);
    cnot_rr<0, 1>(v);
}

__global__ void __launch_bounds__(256) pqc_kernel(
    const int* __restrict__ subgraphs, const int* __restrict__ edge_ids,
    const int* __restrict__ batch,
    const float* __restrict__ Wu1, const float* __restrict__ bu1,
    const float* __restrict__ Wu2, const float* __restrict__ bu2,
    const float* __restrict__ Wh1, const float* __restrict__ bh1,
    const float* __restrict__ Wh2, const float* __restrict__ bh2,
    float* __restrict__ out) {
    __shared__ float2 sG[52];
    __shared__ float sW1[384];
    __shared__ float sb1[128];
    __shared__ float sW2[256];
    __shared__ float sb2[2];
    __shared__ float sAcc[NUM_GRAPHS * 3];
    __shared__ int sLast;
    int tid = threadIdx.x;
    if (tid < 52) sG[tid] = g_gates[tid];
    for (int k = tid; k < 384; k += 256) sW1[k] = Wu1[k];
    if (tid < 128) sb1[tid] = bu1[tid];
    if (tid >= 128) sW2[tid - 128] = Wu2[tid - 128];
    if (tid < 128) sW2[128 + tid] = Wu2[128 + tid];
    if (tid < 2) sb2[tid] = bu2[tid];
    if (tid < NUM_GRAPHS * 3) sAcc[tid] = 0.f;
    __syncthreads();

    int lane = tid & 31;
    int s = blockIdx.x * 8 + (tid >> 5);

    // ---- initial product state ----
    int e0 = edge_ids[3 * s], e1 = edge_ids[3 * s + 1], e2 = edge_ids[3 * s + 2];
    int n0 = subgraphs[4 * s], n1 = subgraphs[4 * s + 1],
        n2 = subgraphs[4 * s + 2], n3 = subgraphs[4 * s + 3];

    float x0c = g_x[2 * n0], x1c = g_x[2 * n0 + 1];   // x[center] (wire-3 angles)

    float2 lf = wire_factor(g_e[2 * e0], g_e[2 * e0 + 1], (lane >> 4) & 1);
    lf = cmul(lf, wire_factor(g_e[2 * e1], g_e[2 * e1 + 1], (lane >> 3) & 1));
    lf = cmul(lf, wire_factor(g_e[2 * e2], g_e[2 * e2 + 1], (lane >> 2) & 1));
    lf = cmul(lf, wire_factor(g_x[2 * n2], g_x[2 * n2 + 1], (lane >> 1) & 1));
    lf = cmul(lf, wire_factor(g_x[2 * n3], g_x[2 * n3 + 1], lane & 1));
    float2 f3_0 = wire_factor(x0c, x1c, 0);
    float2 f3_1 = wire_factor(x0c, x1c, 1);
    float2 f4_0 = wire_factor(g_x[2 * n1], g_x[2 * n1 + 1], 0);
    float2 f4_1 = wire_factor(g_x[2 * n1], g_x[2 * n1 + 1], 1);

    float2 v[16];
#pragma unroll
    for (int r = 0; r < 16; r++) v[r] = make_float2(0.f, 0.f);
    v[0]  = cmul(lf, cmul(f4_0, f3_0));
    v[4]  = cmul(lf, cmul(f4_1, f3_0));
    v[8]  = cmul(lf, cmul(f4_0, f3_1));
    v[12] = cmul(lf, cmul(f4_1, f3_1));

    // ---- iteration i=0: e = bit8 (L4, mask16), nb = bit4 (R2) ----
    crx_rr<2, 1>(v, sG[0].x, sG[0].y);
    cry_lr<1>(v, sG[1].x, sG[1].y, lane, 16);
    crz_rr<2, 0>(v, sG[2].x, sG[2].y);
    cry_lr<0>(v, sG[3].x, sG[3].y, lane, 16);
    ap_lane(v, &sG[16], lane, 16);
    ap_reg<2>(v, &sG[20]);
    ap_reg<1>(v, &sG[24]);
    cnot_lr<2>(v, lane, 16);
    cnot_rr<2, 1>(v);
    cnot_rl<1>(v, 16);
    ap_reg<1>(v, &sG[28]);
    ap_reg<2>(v, &sG[32]);
    ap_reg<0>(v, &sG[36]);
    cnot_rr<1, 2>(v);
    cnot_rr<2, 0>(v);
    cnot_rr<0, 1>(v);

    // ---- iterations i=1 (e=L3 mask8, nb=L1 mask2), i=2 (e=L2 mask4, nb=L0 mask1) ----
    iter_lane<8, 2>(v, sG, sG, lane);
    iter_lane<4, 1>(v, sG, sG, lane);

    // ---- final sel on bits 5(R3), 1(R1), 0(R0) ----
    ap_reg<3>(v, &sG[40]);
    ap_reg<1>(v, &sG[44]);
    ap_reg<0>(v, &sG[48]);
    cnot_rr<3, 1>(v);
    cnot_rr<1, 0>(v);
    cnot_rr<0, 3>(v);

    // ---- expectation (all lanes get total via butterfly) ----
    float part = 0.f;
#pragma unroll
    for (int r = 0; r < 8; r++)
        part += v[r].x * v[r + 8].x + v[r].y * v[r + 8].y;
#pragma unroll
    for (int o = 16; o; o >>= 1) part += __shfl_xor_sync(0xffffffffu, part, o);
    float aggr = 2.0f * part;

    // ---- fused update MLP: in = [x0c, x1c, aggr], 4 hidden units per lane ----
    float o0 = 0.f, o1 = 0.f;
#pragma unroll
    for (int k = 0; k < 4; k++) {
        int h = lane + 32 * k;
        float a = fmaf(x0c, sW1[h],
                  fmaf(x1c, sW1[128 + h],
                  fmaf(aggr, sW1[256 + h], sb1[h])));
        a = a > 0.f ? a : 0.01f * a;
        o0 = fmaf(a, sW2[2 * h], o0);
        o1 = fmaf(a, sW2[2 * h + 1], o1);
    }
#pragma unroll
    for (int o = 16; o; o >>= 1) {
        o0 += __shfl_xor_sync(0xffffffffu, o0, o);
        o1 += __shfl_xor_sync(0xffffffffu, o1, o);
    }
    if (lane == 0) {
        o0 += sb2[0]; o1 += sb2[1];
        int gu = batch[n0];
        int gx = batch[s];
        atomicAdd(&sAcc[3 * gu + 0], o0);
        atomicAdd(&sAcc[3 * gu + 1], o1);
        atomicAdd(&sAcc[3 * gx + 0], g_x[2 * s]);
        atomicAdd(&sAcc[3 * gx + 1], g_x[2 * s + 1]);
        atomicAdd(&sAcc[3 * gx + 2], 1.f);
    }
    __syncthreads();

    // block -> global accumulation
    if (tid < NUM_GRAPHS) {
        atomicAdd(&g_gsum[2 * tid],     sAcc[3 * tid + 0]);
        atomicAdd(&g_gsum[2 * tid + 1], sAcc[3 * tid + 1]);
        atomicAdd(&g_gcnt[tid],         sAcc[3 * tid + 2]);
        __threadfence();
    }
    __syncthreads();
    if (tid == 0) {
        int old = atomicAdd(&g_done, 1);
        sLast = (old == PQC_BLOCKS - 1);
        __threadfence();
    }
    __syncthreads();

    // last block computes the head MLP for all 16 graphs
    if (sLast && tid < NUM_GRAPHS) {
        int g = tid;
        float cnt = __ldcg(&g_gcnt[g]);
        float g0 = __ldcg(&g_gsum[2 * g]) / cnt;
        float g1 = __ldcg(&g_gsum[2 * g + 1]) / cnt;
        float h0 = g0 * Wh1[0] + g1 * Wh1[2] + bh1[0];
        float h1 = g0 * Wh1[1] + g1 * Wh1[3] + bh1[1];
        h0 = h0 > 0.f ? h0 : 0.01f * h0;
        h1 = h1 > 0.f ? h1 : 0.01f * h1;
        out[2 * g]     = h0 * Wh2[0] + h1 * Wh2[2] + bh2[0];
        out[2 * g + 1] = h0 * Wh2[1] + h1 * Wh2[3] + bh2[1];
    }
}

// ---------------- launch ----------------
extern "C" void kernel_launch(void* const* d_in, const int* in_sizes, int n_in,
                              void* d_out, int out_size) {
    const float* node_feat = (const float*)d_in[0];
    const float* edge_attr = (const float*)d_in[1];
    const float* Wn1 = (const float*)d_in[2];
    const float* bn1 = (const float*)d_in[3];
    const float* Wn2 = (const float*)d_in[4];
    const float* bn2 = (const float*)d_in[5];
    const float* We1 = (const float*)d_in[6];
    const float* be1 = (const float*)d_in[7];
    const float* We2 = (const float*)d_in[8];
    const float* be2 = (const float*)d_in[9];
    const float* strong = (const float*)d_in[10];
    const float* inits  = (const float*)d_in[11];
    const float* update = (const float*)d_in[12];
    const float* Wu1 = (const float*)d_in[13];
    const float* bu1 = (const float*)d_in[14];
    const float* Wu2 = (const float*)d_in[15];
    const float* bu2 = (const float*)d_in[16];
    const float* Wh1 = (const float*)d_in[17];
    const float* bh1 = (const float*)d_in[18];
    const float* Wh2 = (const float*)d_in[19];
    const float* bh2 = (const float*)d_in[20];
    const int* subgraphs = (const int*)d_in[21];
    const int* edge_ids  = (const int*)d_in[22];
    const int* batch     = (const int*)d_in[23];
    float* out = (float*)d_out;

    mlp_fused_kernel<<<64, 256>>>(node_feat, Wn1, bn1, Wn2, bn2,
                                  edge_attr, We1, be1, We2, be2,
                                  strong, inits, update);
    pqc_kernel<<<PQC_BLOCKS, 256>>>(subgraphs, edge_ids, batch,
                                    Wu1, bu1, Wu2, bu2,
                                    Wh1, bh1, Wh2, bh2, out);
}

// round 4
// speedup vs baseline: 3.8354x; 1.2615x over previous
#include <cuda_runtime.h>
#include <math.h>

#define PI_F 3.14159265358979323846f
#define N_NODES 4096
#define N_EDGES 12288
#define NUM_GRAPHS 16
#define PQC_BLOCKS 512

// ---------------- device scratch ----------------
__device__ float  g_x[N_NODES * 2];
__device__ float  g_e[N_EDGES * 2];
__device__ float2 g_gates[52];   // [0..3]: (c,s) of CRX,CRY1,CRZ,CRY2 targets; [16..51]: 9 rot matrices
__device__ float  g_gsum[NUM_GRAPHS * 2];
__device__ float  g_gcnt[NUM_GRAPHS];
__device__ int    g_done;

// ---------------- complex helpers ----------------
__device__ __forceinline__ float2 cmul(float2 a, float2 b) {
    return make_float2(fmaf(a.x, b.x, -(a.y * b.y)), fmaf(a.x, b.y, a.y * b.x));
}
__device__ __forceinline__ float2 cfma(float2 a, float2 b, float2 c) {   // a*b + c
    return make_float2(fmaf(a.x, b.x, fmaf(-a.y, b.y, c.x)),
                       fmaf(a.x, b.y, fmaf( a.y, b.x, c.y)));
}

// ---------------- gate precompute ----------------
__device__ void make_rot(const float* w, float2* m) {
    float phi = w[0], th = w[1], om = w[2];
    float c, s; sincosf(th * 0.5f, &s, &c);
    float sa, ca, sb, cb;
    sincosf((phi + om) * 0.5f, &sa, &ca);
    sincosf((phi - om) * 0.5f, &sb, &cb);
    m[0] = make_float2(c * ca, -c * sa);
    m[1] = make_float2(-s * cb, -s * sb);
    m[2] = make_float2(s * cb, -s * sb);
    m[3] = make_float2(c * ca, c * sa);
}

__device__ void prep_gates(const float* strong, const float* inits, const float* update) {
    float c, s;
    sincosf(inits[0] * 0.5f, &s, &c); g_gates[0] = make_float2(c, s);  // CRX target
    sincosf(inits[1] * 0.5f, &s, &c); g_gates[1] = make_float2(c, s);  // CRY1
    sincosf(inits[2] * 0.5f, &s, &c); g_gates[2] = make_float2(c, s);  // CRZ
    sincosf(inits[3] * 0.5f, &s, &c); g_gates[3] = make_float2(c, s);  // CRY2
    for (int j = 0; j < 3; j++) make_rot(strong + j * 3,     &g_gates[(4 + j) * 4]);
    for (int j = 0; j < 3; j++) make_rot(strong + 9 + j * 3, &g_gates[(7 + j) * 4]);
    for (int j = 0; j < 3; j++) make_rot(update + j * 3,     &g_gates[(10 + j) * 4]);
}

// ---------------- fused node+edge MLP (+ prep) ----------------
template <int NI>
__device__ __forceinline__ void mlp_row(const float* __restrict__ inp, int r,
                                        const float* sW1, const float* sb1,
                                        const float* sW2, const float* sb2,
                                        float* __restrict__ outp) {
    float in[NI];
#pragma unroll
    for (int i = 0; i < NI; i++) in[i] = inp[r * NI + i];
    float o0 = sb2[0], o1 = sb2[1];
#pragma unroll 4
    for (int h = 0; h < 128; h++) {
        float a = sb1[h];
#pragma unroll
        for (int i = 0; i < NI; i++) a = fmaf(in[i], sW1[i * 128 + h], a);
        a = a > 0.f ? a : 0.01f * a;
        o0 = fmaf(a, sW2[2 * h], o0);
        o1 = fmaf(a, sW2[2 * h + 1], o1);
    }
    outp[2 * r]     = tanhf(o0) * PI_F;
    outp[2 * r + 1] = tanhf(o1) * PI_F;
}

__global__ void __launch_bounds__(256) mlp_fused_kernel(
    const float* __restrict__ node_feat,
    const float* __restrict__ Wn1, const float* __restrict__ bn1,
    const float* __restrict__ Wn2, const float* __restrict__ bn2,
    const float* __restrict__ edge_attr,
    const float* __restrict__ We1, const float* __restrict__ be1,
    const float* __restrict__ We2, const float* __restrict__ be2,
    const float* __restrict__ strong, const float* __restrict__ inits,
    const float* __restrict__ update) {
    __shared__ float sW1[8 * 128];
    __shared__ float sb1[128];
    __shared__ float sW2[256];
    __shared__ float sb2[2];
    int b = blockIdx.x, tid = threadIdx.x;
    bool isNode = (b < 16);
    const float* W1 = isNode ? Wn1 : We1;
    const float* b1 = isNode ? bn1 : be1;
    const float* W2 = isNode ? Wn2 : We2;
    const float* b2 = isNode ? bn2 : be2;
    int ni = isNode ? 8 : 4;
    for (int k = tid; k < ni * 128; k += 256) sW1[k] = W1[k];
    for (int k = tid; k < 128; k += 256) sb1[k] = b1[k];
    for (int k = tid; k < 256; k += 256) sW2[k] = W2[k];
    if (tid < 2) sb2[tid] = b2[tid];

    if (b == 0) {
        if (tid < NUM_GRAPHS) {
            g_gsum[2 * tid] = 0.f; g_gsum[2 * tid + 1] = 0.f; g_gcnt[tid] = 0.f;
        }
        if (tid == 33) g_done = 0;
        if (tid == 32) prep_gates(strong, inits, update);
    }
    __syncthreads();

    if (isNode)
        mlp_row<8>(node_feat, b * 256 + tid, sW1, sb1, sW2, sb2, g_x);
    else
        mlp_row<4>(edge_attr, (b - 16) * 256 + tid, sW1, sb1, sW2, sb2, g_e);
}

// ================= PQC: warp-per-state, all-register gates =================
// Register bits hold the ACTIVE wires of the current iteration:
//   R0(bit0)=a2(w8), R1(bit1)=a1(w7), R2(bit2)=nb(w4+i), R3(bit3)=e(w i)
// Lane bits hold the 5 inactive wires; reg<->lane bit swaps retarget between iters.

// generic 1q gate on register bit J (Rot matrix from smem)
template <int J>
__device__ __forceinline__ void ap_reg(float2* v, const float2* U) {
    float2 u0 = U[0], u1 = U[1], u2 = U[2], u3 = U[3];
#pragma unroll
    for (int r = 0; r < 16; r++) {
        if ((r >> J) & 1) continue;
        int r2 = r | (1 << J);
        float2 a = v[r], b = v[r2];
        v[r]  = cfma(u1, b, cmul(u0, a));
        v[r2] = cfma(u3, b, cmul(u2, a));
    }
}
// controlled RX: active where control=1; target [[c,-is],[-is,c]]
template <int C, int T>
__device__ __forceinline__ void crx_rr(float2* v, float c, float s) {
#pragma unroll
    for (int r = 0; r < 16; r++) {
        if (!((r >> C) & 1) || ((r >> T) & 1)) continue;
        int r2 = r | (1 << T);
        float2 a = v[r], b = v[r2];
        v[r]  = make_float2(fmaf(c, a.x,  s * b.y), fmaf(c, a.y, -s * b.x));
        v[r2] = make_float2(fmaf(c, b.x,  s * a.y), fmaf(c, b.y, -s * a.x));
    }
}
// controlled RY: target [[c,-s],[s,c]] (real)
template <int C, int T>
__device__ __forceinline__ void cry_rr(float2* v, float c, float s) {
#pragma unroll
    for (int r = 0; r < 16; r++) {
        if (!((r >> C) & 1) || ((r >> T) & 1)) continue;
        int r2 = r | (1 << T);
        float2 a = v[r], b = v[r2];
        v[r]  = make_float2(fmaf(c, a.x, -s * b.x), fmaf(c, a.y, -s * b.y));
        v[r2] = make_float2(fmaf(c, b.x,  s * a.x), fmaf(c, b.y,  s * a.y));
    }
}
// controlled RZ: target diag(e^{-is}, e^{+is})
template <int C, int T>
__device__ __forceinline__ void crz_rr(float2* v, float c, float s) {
#pragma unroll
    for (int r = 0; r < 16; r++) {
        if (!((r >> C) & 1)) continue;
        float sg = ((r >> T) & 1) ? -s : s;
        float2 a = v[r];
        v[r] = make_float2(fmaf(c, a.x, sg * a.y), fmaf(c, a.y, -sg * a.x));
    }
}
// CNOT reg->reg: pure register permutation (free after unroll)
template <int C, int T>
__device__ __forceinline__ void cnot_rr(float2* v) {
#pragma unroll
    for (int r = 0; r < 16; r++) {
        if (!((r >> C) & 1) || ((r >> T) & 1)) continue;
        int r2 = r | (1 << T);
        float2 t = v[r]; v[r] = v[r2]; v[r2] = t;
    }
}
// swap register bit J with lane bit (mask M): 16 SHFL total
template <int J>
__device__ __forceinline__ void swap_reg_lane(float2* v, int lane, int mask) {
    bool b = lane & mask;
#pragma unroll
    for (int r = 0; r < 16; r++) {
        if ((r >> J) & 1) continue;
        int r2 = r | (1 << J);
        float2 send = b ? v[r] : v[r2];
        float2 recv;
        recv.x = __shfl_xor_sync(0xffffffffu, send.x, mask);
        recv.y = __shfl_xor_sync(0xffffffffu, send.y, mask);
        if (b) v[r] = recv; else v[r2] = recv;
    }
}

__device__ __forceinline__ float2 wire_factor(float ry, float rz, int bit) {
    float sy, cy, sz, cz;
    sincosf(0.5f * ry, &sy, &cy);
    sincosf(0.5f * rz, &sz, &cz);
    return bit ? make_float2(sy * cz, sy * sz) : make_float2(cy * cz, -cy * sz);
}

// one full ctrl+sel+sel iteration, all wires in register bits
__device__ __forceinline__ void iter_regs(float2* v, const float2* sG) {
    crx_rr<2, 1>(v, sG[0].x, sG[0].y);   // CRX(nb -> a1)
    cry_rr<3, 1>(v, sG[1].x, sG[1].y);   // CRY(e  -> a1)
    crz_rr<2, 0>(v, sG[2].x, sG[2].y);   // CRZ(nb -> a2)
    cry_rr<3, 0>(v, sG[3].x, sG[3].y);   // CRY(e  -> a2)
    // sel strong[0] on [e, nb, a1]
    ap_reg<3>(v, &sG[16]);
    ap_reg<2>(v, &sG[20]);
    ap_reg<1>(v, &sG[24]);
    cnot_rr<3, 2>(v);
    cnot_rr<2, 1>(v);
    cnot_rr<1, 3>(v);
    // sel strong[1] on [a1, nb, a2]
    ap_reg<1>(v, &sG[28]);
    ap_reg<2>(v, &sG[32]);
    ap_reg<0>(v, &sG[36]);
    cnot_rr<1, 2>(v);
    cnot_rr<2, 0>(v);
    cnot_rr<0, 1>(v);
}

__global__ void __launch_bounds__(256) pqc_kernel(
    const int* __restrict__ subgraphs, const int* __restrict__ edge_ids,
    const int* __restrict__ batch,
    const float* __restrict__ Wu1, const float* __restrict__ bu1,
    const float* __restrict__ Wu2, const float* __restrict__ bu2,
    const float* __restrict__ Wh1, const float* __restrict__ bh1,
    const float* __restrict__ Wh2, const float* __restrict__ bh2,
    float* __restrict__ out) {
    __shared__ float2 sG[52];
    __shared__ float sW1[384];
    __shared__ float sb1[128];
    __shared__ float sW2[256];
    __shared__ float sb2[2];
    __shared__ float sAcc[NUM_GRAPHS * 3];
    __shared__ int sLast;
    int tid = threadIdx.x;
    if (tid < 52) sG[tid] = g_gates[tid];
    for (int k = tid; k < 384; k += 256) sW1[k] = Wu1[k];
    if (tid < 128) sb1[tid] = bu1[tid];
    if (tid >= 128) sW2[tid - 128] = Wu2[tid - 128];
    if (tid < 128) sW2[128 + tid] = Wu2[128 + tid];
    if (tid < 2) sb2[tid] = bu2[tid];
    if (tid < NUM_GRAPHS * 3) sAcc[tid] = 0.f;
    __syncthreads();

    int lane = tid & 31;
    int s = blockIdx.x * 8 + (tid >> 5);

    // ---- initial product state ----
    // reg bits: R0=a2=0, R1=a1=0, R2=w4(n1), R3=w0(e0)
    // lane bits: L4(16)=w1(e1), L3(8)=w2(e2), L2(4)=w3(n0), L1(2)=w5(n2), L0(1)=w6(n3)
    int e0 = edge_ids[3 * s], e1 = edge_ids[3 * s + 1], e2 = edge_ids[3 * s + 2];
    int n0 = subgraphs[4 * s], n1 = subgraphs[4 * s + 1],
        n2 = subgraphs[4 * s + 2], n3 = subgraphs[4 * s + 3];

    float x0c = g_x[2 * n0], x1c = g_x[2 * n0 + 1];   // x[center]

    float2 lf = wire_factor(g_e[2 * e1], g_e[2 * e1 + 1], (lane >> 4) & 1);
    lf = cmul(lf, wire_factor(g_e[2 * e2], g_e[2 * e2 + 1], (lane >> 3) & 1));
    lf = cmul(lf, wire_factor(x0c, x1c, (lane >> 2) & 1));
    lf = cmul(lf, wire_factor(g_x[2 * n2], g_x[2 * n2 + 1], (lane >> 1) & 1));
    lf = cmul(lf, wire_factor(g_x[2 * n3], g_x[2 * n3 + 1], lane & 1));
    float2 f0_0 = wire_factor(g_e[2 * e0], g_e[2 * e0 + 1], 0);   // w0 -> R3
    float2 f0_1 = wire_factor(g_e[2 * e0], g_e[2 * e0 + 1], 1);
    float2 f4_0 = wire_factor(g_x[2 * n1], g_x[2 * n1 + 1], 0);   // w4 -> R2
    float2 f4_1 = wire_factor(g_x[2 * n1], g_x[2 * n1 + 1], 1);

    float2 v[16];
#pragma unroll
    for (int r = 0; r < 16; r++) v[r] = make_float2(0.f, 0.f);
    v[0]  = cmul(lf, cmul(f4_0, f0_0));
    v[4]  = cmul(lf, cmul(f4_1, f0_0));
    v[8]  = cmul(lf, cmul(f4_0, f0_1));
    v[12] = cmul(lf, cmul(f4_1, f0_1));

    // ---- iteration 0: e=w0(R3), nb=w4(R2) ----
    iter_regs(v, sG);
    // retarget: R3: w0<->w1(L4), R2: w4<->w5(L1)
    swap_reg_lane<3>(v, lane, 16);
    swap_reg_lane<2>(v, lane, 2);
    // ---- iteration 1: e=w1(R3), nb=w5(R2) ----
    iter_regs(v, sG);
    // retarget: R3: w1<->w2(L3), R2: w5<->w6(L0)
    swap_reg_lane<3>(v, lane, 8);
    swap_reg_lane<2>(v, lane, 1);
    // ---- iteration 2: e=w2(R3), nb=w6(R2) ----
    iter_regs(v, sG);
    // retarget: R3: w2<->w3(L2)
    swap_reg_lane<3>(v, lane, 4);

    // ---- final sel(update) on [w3(R3), a1(R1), a2(R0)] ----
    ap_reg<3>(v, &sG[40]);
    ap_reg<1>(v, &sG[44]);
    ap_reg<0>(v, &sG[48]);
    cnot_rr<3, 1>(v);
    cnot_rr<1, 0>(v);
    cnot_rr<0, 3>(v);

    // ---- expectation on w3 = R3 (all lanes get total via butterfly) ----
    float part = 0.f;
#pragma unroll
    for (int r = 0; r < 8; r++)
        part += v[r].x * v[r + 8].x + v[r].y * v[r + 8].y;
#pragma unroll
    for (int o = 16; o; o >>= 1) part += __shfl_xor_sync(0xffffffffu, part, o);
    float aggr = 2.0f * part;

    // ---- fused update MLP: in = [x0c, x1c, aggr], 4 hidden units per lane ----
    float o0 = 0.f, o1 = 0.f;
#pragma unroll
    for (int k = 0; k < 4; k++) {
        int h = lane + 32 * k;
        float a = fmaf(x0c, sW1[h],
                  fmaf(x1c, sW1[128 + h],
                  fmaf(aggr, sW1[256 + h], sb1[h])));
        a = a > 0.f ? a : 0.01f * a;
        o0 = fmaf(a, sW2[2 * h], o0);
        o1 = fmaf(a, sW2[2 * h + 1], o1);
    }
#pragma unroll
    for (int o = 16; o; o >>= 1) {
        o0 += __shfl_xor_sync(0xffffffffu, o0, o);
        o1 += __shfl_xor_sync(0xffffffffu, o1, o);
    }
    if (lane == 0) {
        o0 += sb2[0]; o1 += sb2[1];
        int gu = batch[n0];
        int gx = batch[s];
        atomicAdd(&sAcc[3 * gu + 0], o0);
        atomicAdd(&sAcc[3 * gu + 1], o1);
        atomicAdd(&sAcc[3 * gx + 0], g_x[2 * s]);
        atomicAdd(&sAcc[3 * gx + 1], g_x[2 * s + 1]);
        atomicAdd(&sAcc[3 * gx + 2], 1.f);
    }
    __syncthreads();

    // block -> global accumulation
    if (tid < NUM_GRAPHS) {
        atomicAdd(&g_gsum[2 * tid],     sAcc[3 * tid + 0]);
        atomicAdd(&g_gsum[2 * tid + 1], sAcc[3 * tid + 1]);
        atomicAdd(&g_gcnt[tid],         sAcc[3 * tid + 2]);
        __threadfence();
    }
    __syncthreads();
    if (tid == 0) {
        int old = atomicAdd(&g_done, 1);
        sLast = (old == PQC_BLOCKS - 1);
        __threadfence();
    }
    __syncthreads();

    // last block computes the head MLP
    if (sLast && tid < NUM_GRAPHS) {
        int g = tid;
        float cnt = __ldcg(&g_gcnt[g]);
        float g0 = __ldcg(&g_gsum[2 * g]) / cnt;
        float g1 = __ldcg(&g_gsum[2 * g + 1]) / cnt;
        float h0 = g0 * Wh1[0] + g1 * Wh1[2] + bh1[0];
        float h1 = g0 * Wh1[1] + g1 * Wh1[3] + bh1[1];
        h0 = h0 > 0.f ? h0 : 0.01f * h0;
        h1 = h1 > 0.f ? h1 : 0.01f * h1;
        out[2 * g]     = h0 * Wh2[0] + h1 * Wh2[2] + bh2[0];
        out[2 * g + 1] = h0 * Wh2[1] + h1 * Wh2[3] + bh2[1];
    }
}

// ---------------- launch ----------------
extern "C" void kernel_launch(void* const* d_in, const int* in_sizes, int n_in,
                              void* d_out, int out_size) {
    const float* node_feat = (const float*)d_in[0];
    const float* edge_attr = (const float*)d_in[1];
    const float* Wn1 = (const float*)d_in[2];
    const float* bn1 = (const float*)d_in[3];
    const float* Wn2 = (const float*)d_in[4];
    const float* bn2 = (const float*)d_in[5];
    const float* We1 = (const float*)d_in[6];
    const float* be1 = (const float*)d_in[7];
    const float* We2 = (const float*)d_in[8];
    const float* be2 = (const float*)d_in[9];
    const float* strong = (const float*)d_in[10];
    const float* inits  = (const float*)d_in[11];
    const float* update = (const float*)d_in[12];
    const float* Wu1 = (const float*)d_in[13];
    const float* bu1 = (const float*)d_in[14];
    const float* Wu2 = (const float*)d_in[15];
    const float* bu2 = (const float*)d_in[16];
    const float* Wh1 = (const float*)d_in[17];
    const float* bh1 = (const float*)d_in[18];
    const float* Wh2 = (const float*)d_in[19];
    const float* bh2 = (const float*)d_in[20];
    const int* subgraphs = (const int*)d_in[21];
    const int* edge_ids  = (const int*)d_in[22];
    const int* batch     = (const int*)d_in[23];
    float* out = (float*)d_out;

    mlp_fused_kernel<<<64, 256>>>(node_feat, Wn1, bn1, Wn2, bn2,
                                  edge_attr, We1, be1, We2, be2,
                                  strong, inits, update);
    pqc_kernel<<<PQC_BLOCKS, 256>>>(subgraphs, edge_ids, batch,
                                    Wu1, bu1, Wu2, bu2,
                                    Wh1, bh1, Wh2, bh2, out);
}

// round 5
// speedup vs baseline: 4.5300x; 1.1811x over previous
#include <cuda_runtime.h>
#include <math.h>

#define PI_F 3.14159265358979323846f
#define N_NODES 4096
#define N_EDGES 12288
#define NUM_GRAPHS 16
#define PQC_BLOCKS 512

// ---------------- device scratch ----------------
__device__ float  g_x[N_NODES * 2];     // node angles (needed for update-MLP input & segment sum)
__device__ float4 g_x4[N_NODES];        // node wire amplitudes (a0.x,a0.y,a1.x,a1.y)
__device__ float4 g_e4[N_EDGES];        // edge wire amplitudes
__device__ float2 g_gates[52];          // [0..3]: (c,s) of CRX,CRY1,CRZ,CRY2; [16..51]: 9 rot matrices
__device__ float2 g_w[64];              // 4 precomputed iter0 output columns (16 each)
__device__ float  g_gsum[NUM_GRAPHS * 2];
__device__ float  g_gcnt[NUM_GRAPHS];
__device__ int    g_done;

// ---------------- complex helpers ----------------
__device__ __forceinline__ float2 cmul(float2 a, float2 b) {
    return make_float2(fmaf(a.x, b.x, -(a.y * b.y)), fmaf(a.x, b.y, a.y * b.x));
}
__device__ __forceinline__ float2 cfma(float2 a, float2 b, float2 c) {   // a*b + c
    return make_float2(fmaf(a.x, b.x, fmaf(-a.y, b.y, c.x)),
                       fmaf(a.x, b.y, fmaf( a.y, b.x, c.y)));
}

// ================= PQC register-gate primitives =================
// Register bits hold the ACTIVE wires: R0=a2, R1=a1, R2=nb, R3=e

template <int J>
__device__ __forceinline__ void ap_reg(float2* v, const float2* U) {
    float2 u0 = U[0], u1 = U[1], u2 = U[2], u3 = U[3];
#pragma unroll
    for (int r = 0; r < 16; r++) {
        if ((r >> J) & 1) continue;
        int r2 = r | (1 << J);
        float2 a = v[r], b = v[r2];
        v[r]  = cfma(u1, b, cmul(u0, a));
        v[r2] = cfma(u3, b, cmul(u2, a));
    }
}
template <int C, int T>
__device__ __forceinline__ void crx_rr(float2* v, float c, float s) {
#pragma unroll
    for (int r = 0; r < 16; r++) {
        if (!((r >> C) & 1) || ((r >> T) & 1)) continue;
        int r2 = r | (1 << T);
        float2 a = v[r], b = v[r2];
        v[r]  = make_float2(fmaf(c, a.x,  s * b.y), fmaf(c, a.y, -s * b.x));
        v[r2] = make_float2(fmaf(c, b.x,  s * a.y), fmaf(c, b.y, -s * a.x));
    }
}
template <int C, int T>
__device__ __forceinline__ void cry_rr(float2* v, float c, float s) {
#pragma unroll
    for (int r = 0; r < 16; r++) {
        if (!((r >> C) & 1) || ((r >> T) & 1)) continue;
        int r2 = r | (1 << T);
        float2 a = v[r], b = v[r2];
        v[r]  = make_float2(fmaf(c, a.x, -s * b.x), fmaf(c, a.y, -s * b.y));
        v[r2] = make_float2(fmaf(c, b.x,  s * a.x), fmaf(c, b.y,  s * a.y));
    }
}
template <int C, int T>
__device__ __forceinline__ void crz_rr(float2* v, float c, float s) {
#pragma unroll
    for (int r = 0; r < 16; r++) {
        if (!((r >> C) & 1)) continue;
        float sg = ((r >> T) & 1) ? -s : s;
        float2 a = v[r];
        v[r] = make_float2(fmaf(c, a.x, sg * a.y), fmaf(c, a.y, -sg * a.x));
    }
}
template <int C, int T>
__device__ __forceinline__ void cnot_rr(float2* v) {
#pragma unroll
    for (int r = 0; r < 16; r++) {
        if (!((r >> C) & 1) || ((r >> T) & 1)) continue;
        int r2 = r | (1 << T);
        float2 t = v[r]; v[r] = v[r2]; v[r2] = t;
    }
}
template <int J>
__device__ __forceinline__ void swap_reg_lane(float2* v, int lane, int mask) {
    bool b = lane & mask;
#pragma unroll
    for (int r = 0; r < 16; r++) {
        if ((r >> J) & 1) continue;
        int r2 = r | (1 << J);
        float2 send = b ? v[r] : v[r2];
        float2 recv;
        recv.x = __shfl_xor_sync(0xffffffffu, send.x, mask);
        recv.y = __shfl_xor_sync(0xffffffffu, send.y, mask);
        if (b) v[r] = recv; else v[r2] = recv;
    }
}

// one full ctrl+sel+sel iteration, all wires in register bits
__device__ __forceinline__ void iter_regs(float2* v, const float2* sG) {
    crx_rr<2, 1>(v, sG[0].x, sG[0].y);   // CRX(nb -> a1)
    cry_rr<3, 1>(v, sG[1].x, sG[1].y);   // CRY(e  -> a1)
    crz_rr<2, 0>(v, sG[2].x, sG[2].y);   // CRZ(nb -> a2)
    cry_rr<3, 0>(v, sG[3].x, sG[3].y);   // CRY(e  -> a2)
    ap_reg<3>(v, &sG[16]);
    ap_reg<2>(v, &sG[20]);
    ap_reg<1>(v, &sG[24]);
    cnot_rr<3, 2>(v);
    cnot_rr<2, 1>(v);
    cnot_rr<1, 3>(v);
    ap_reg<1>(v, &sG[28]);
    ap_reg<2>(v, &sG[32]);
    ap_reg<0>(v, &sG[36]);
    cnot_rr<1, 2>(v);
    cnot_rr<2, 0>(v);
    cnot_rr<0, 1>(v);
}

// ---------------- gate precompute ----------------
__device__ void make_rot(const float* w, float2* m) {
    float phi = w[0], th = w[1], om = w[2];
    float c, s; sincosf(th * 0.5f, &s, &c);
    float sa, ca, sb, cb;
    sincosf((phi + om) * 0.5f, &sa, &ca);
    sincosf((phi - om) * 0.5f, &sb, &cb);
    m[0] = make_float2(c * ca, -c * sa);
    m[1] = make_float2(-s * cb, -s * sb);
    m[2] = make_float2(s * cb, -s * sb);
    m[3] = make_float2(c * ca, c * sa);
}

__device__ void prep_gates(const float* strong, const float* inits, const float* update) {
    float c, s;
    sincosf(inits[0] * 0.5f, &s, &c); g_gates[0] = make_float2(c, s);
    sincosf(inits[1] * 0.5f, &s, &c); g_gates[1] = make_float2(c, s);
    sincosf(inits[2] * 0.5f, &s, &c); g_gates[2] = make_float2(c, s);
    sincosf(inits[3] * 0.5f, &s, &c); g_gates[3] = make_float2(c, s);
    for (int j = 0; j < 3; j++) make_rot(strong + j * 3,     &g_gates[(4 + j) * 4]);
    for (int j = 0; j < 3; j++) make_rot(strong + 9 + j * 3, &g_gates[(7 + j) * 4]);
    for (int j = 0; j < 3; j++) make_rot(update + j * 3,     &g_gates[(10 + j) * 4]);
}

// ---------------- fused node+edge MLP (+ prep + W columns) ----------------
template <int NI, bool IS_NODE>
__device__ __forceinline__ void mlp_row(const float* __restrict__ inp, int r,
                                        const float* sW1, const float* sb1,
                                        const float* sW2, const float* sb2) {
    float in[NI];
#pragma unroll
    for (int i = 0; i < NI; i++) in[i] = inp[r * NI + i];
    float o0 = sb2[0], o1 = sb2[1];
#pragma unroll 4
    for (int h = 0; h < 128; h++) {
        float a = sb1[h];
#pragma unroll
        for (int i = 0; i < NI; i++) a = fmaf(in[i], sW1[i * 128 + h], a);
        a = a > 0.f ? a : 0.01f * a;
        o0 = fmaf(a, sW2[2 * h], o0);
        o1 = fmaf(a, sW2[2 * h + 1], o1);
    }
    float t0 = tanhf(o0) * PI_F;   // ry
    float t1 = tanhf(o1) * PI_F;   // rz
    float sy, cy, sz, cz;
    sincosf(0.5f * t0, &sy, &cy);
    sincosf(0.5f * t1, &sz, &cz);
    // amp0 = cy*e^{-i z/2}, amp1 = sy*e^{+i z/2}
    float4 amps = make_float4(cy * cz, -cy * sz, sy * cz, sy * sz);
    if (IS_NODE) {
        g_x[2 * r] = t0; g_x[2 * r + 1] = t1;
        g_x4[r] = amps;
    } else {
        g_e4[r] = amps;
    }
}

__global__ void __launch_bounds__(128) mlp_fused_kernel(
    const float* __restrict__ node_feat,
    const float* __restrict__ Wn1, const float* __restrict__ bn1,
    const float* __restrict__ Wn2, const float* __restrict__ bn2,
    const float* __restrict__ edge_attr,
    const float* __restrict__ We1, const float* __restrict__ be1,
    const float* __restrict__ We2, const float* __restrict__ be2,
    const float* __restrict__ strong, const float* __restrict__ inits,
    const float* __restrict__ update) {
    __shared__ float sW1[8 * 128];
    __shared__ float sb1[128];
    __shared__ float sW2[256];
    __shared__ float sb2[2];
    int b = blockIdx.x, tid = threadIdx.x;
    bool isNode = (b < 32);
    const float* W1 = isNode ? Wn1 : We1;
    const float* b1 = isNode ? bn1 : be1;
    const float* W2 = isNode ? Wn2 : We2;
    const float* b2 = isNode ? bn2 : be2;
    int ni = isNode ? 8 : 4;
    for (int k = tid; k < ni * 128; k += 128) sW1[k] = W1[k];
    sb1[tid] = b1[tid];
    sW2[tid] = W2[tid]; sW2[128 + tid] = W2[128 + tid];
    if (tid < 2) sb2[tid] = b2[tid];

    if (b == 0) {
        if (tid < NUM_GRAPHS) {
            g_gsum[2 * tid] = 0.f; g_gsum[2 * tid + 1] = 0.f; g_gcnt[tid] = 0.f;
        }
        if (tid == 33) g_done = 0;
        if (tid == 32) prep_gates(strong, inits, update);
    }
    __syncthreads();

    // W columns: U_iter0 applied to basis states e_{8a+4b}, k = 2a+b
    if (b == 0 && tid >= 64 && tid < 68) {
        int k = tid - 64;
        float2 v[16];
#pragma unroll
        for (int r = 0; r < 16; r++) v[r] = make_float2(0.f, 0.f);
        v[((k >> 1) << 3) | ((k & 1) << 2)] = make_float2(1.f, 0.f);
        iter_regs(v, g_gates);
#pragma unroll
        for (int r = 0; r < 16; r++) g_w[k * 16 + r] = v[r];
    }

    if (isNode)
        mlp_row<8, true>(node_feat, b * 128 + tid, sW1, sb1, sW2, sb2);
    else
        mlp_row<4, false>(edge_attr, (b - 32) * 128 + tid, sW1, sb1, sW2, sb2);
}

// ================= PQC kernel =================
__device__ __forceinline__ float2 pick(float4 a, int bit) {
    return bit ? make_float2(a.z, a.w) : make_float2(a.x, a.y);
}

__global__ void __launch_bounds__(256) pqc_kernel(
    const int* __restrict__ subgraphs, const int* __restrict__ edge_ids,
    const int* __restrict__ batch,
    const float* __restrict__ Wu1, const float* __restrict__ bu1,
    const float* __restrict__ Wu2, const float* __restrict__ bu2,
    const float* __restrict__ Wh1, const float* __restrict__ bh1,
    const float* __restrict__ Wh2, const float* __restrict__ bh2,
    float* __restrict__ out) {
    __shared__ float2 sG[52];
    __shared__ float2 sWC[64];
    __shared__ float sW1[384];
    __shared__ float sb1[128];
    __shared__ float sW2[256];
    __shared__ float sb2[2];
    __shared__ float sAcc[NUM_GRAPHS * 3];
    __shared__ int sLast;
    int tid = threadIdx.x;
    if (tid < 52) sG[tid] = g_gates[tid];
    if (tid >= 64 && tid < 128) sWC[tid - 64] = g_w[tid - 64];
    for (int k = tid; k < 384; k += 256) sW1[k] = Wu1[k];
    if (tid < 128) sb1[tid] = bu1[tid];
    if (tid >= 128) sW2[tid - 128] = Wu2[tid - 128];
    if (tid < 128) sW2[128 + tid] = Wu2[128 + tid];
    if (tid < 2) sb2[tid] = bu2[tid];
    if (tid < NUM_GRAPHS * 3) sAcc[tid] = 0.f;
    __syncthreads();

    int lane = tid & 31;
    int s = blockIdx.x * 8 + (tid >> 5);

    // lane bits: L4(16)=w1(e1), L3(8)=w2(e2), L2(4)=w3(n0), L1(2)=w5(n2), L0(1)=w6(n3)
    // reg bits: R3=w0(e0), R2=w4(n1), R1=a1, R0=a2
    int e0 = edge_ids[3 * s], e1 = edge_ids[3 * s + 1], e2 = edge_ids[3 * s + 2];
    int n0 = subgraphs[4 * s], n1 = subgraphs[4 * s + 1],
        n2 = subgraphs[4 * s + 2], n3 = subgraphs[4 * s + 3];

    float x0c = g_x[2 * n0], x1c = g_x[2 * n0 + 1];   // x[center] angles for update MLP

    float2 lf = pick(g_e4[e1], (lane >> 4) & 1);
    lf = cmul(lf, pick(g_e4[e2], (lane >> 3) & 1));
    lf = cmul(lf, pick(g_x4[n0], (lane >> 2) & 1));
    lf = cmul(lf, pick(g_x4[n2], (lane >> 1) & 1));
    lf = cmul(lf, pick(g_x4[n3], lane & 1));
    float4 aw0 = g_e4[e0];   // w0 -> R3
    float4 aw4 = g_x4[n1];   // w4 -> R2

    // post-iter0 state via precomputed columns: c_k = lf * f0_a * f4_b (k = 2a+b)
    float2 c0 = cmul(lf, cmul(pick(aw0, 0), pick(aw4, 0)));
    float2 c1 = cmul(lf, cmul(pick(aw0, 0), pick(aw4, 1)));
    float2 c2 = cmul(lf, cmul(pick(aw0, 1), pick(aw4, 0)));
    float2 c3 = cmul(lf, cmul(pick(aw0, 1), pick(aw4, 1)));

    float2 v[16];
#pragma unroll
    for (int r = 0; r < 16; r++)
        v[r] = cfma(c3, sWC[48 + r],
               cfma(c2, sWC[32 + r],
               cfma(c1, sWC[16 + r],
               cmul(c0, sWC[r]))));

    // retarget: R3: w0<->w1(L4), R2: w4<->w5(L1)
    swap_reg_lane<3>(v, lane, 16);
    swap_reg_lane<2>(v, lane, 2);
    iter_regs(v, sG);                     // iteration 1: e=w1, nb=w5
    // retarget: R3: w1<->w2(L3), R2: w5<->w6(L0)
    swap_reg_lane<3>(v, lane, 8);
    swap_reg_lane<2>(v, lane, 1);
    iter_regs(v, sG);                     // iteration 2: e=w2, nb=w6
    // retarget: R3: w2<->w3(L2)
    swap_reg_lane<3>(v, lane, 4);

    // final sel(update) on [w3(R3), a1(R1), a2(R0)]
    ap_reg<3>(v, &sG[40]);
    ap_reg<1>(v, &sG[44]);
    ap_reg<0>(v, &sG[48]);
    cnot_rr<3, 1>(v);
    cnot_rr<1, 0>(v);
    cnot_rr<0, 3>(v);

    // expectation on w3 = R3
    float part = 0.f;
#pragma unroll
    for (int r = 0; r < 8; r++)
        part += v[r].x * v[r + 8].x + v[r].y * v[r + 8].y;
#pragma unroll
    for (int o = 16; o; o >>= 1) part += __shfl_xor_sync(0xffffffffu, part, o);
    float aggr = 2.0f * part;

    // fused update MLP: in = [x0c, x1c, aggr], 4 hidden units per lane
    float o0 = 0.f, o1 = 0.f;
#pragma unroll
    for (int k = 0; k < 4; k++) {
        int h = lane + 32 * k;
        float a = fmaf(x0c, sW1[h],
                  fmaf(x1c, sW1[128 + h],
                  fmaf(aggr, sW1[256 + h], sb1[h])));
        a = a > 0.f ? a : 0.01f * a;
        o0 = fmaf(a, sW2[2 * h], o0);
        o1 = fmaf(a, sW2[2 * h + 1], o1);
    }
#pragma unroll
    for (int o = 16; o; o >>= 1) {
        o0 += __shfl_xor_sync(0xffffffffu, o0, o);
        o1 += __shfl_xor_sync(0xffffffffu, o1, o);
    }
    if (lane == 0) {
        o0 += sb2[0]; o1 += sb2[1];
        int gu = batch[n0];
        int gx = batch[s];
        atomicAdd(&sAcc[3 * gu + 0], o0);
        atomicAdd(&sAcc[3 * gu + 1], o1);
        atomicAdd(&sAcc[3 * gx + 0], g_x[2 * s]);
        atomicAdd(&sAcc[3 * gx + 1], g_x[2 * s + 1]);
        atomicAdd(&sAcc[3 * gx + 2], 1.f);
    }
    __syncthreads();

    if (tid < NUM_GRAPHS) {
        atomicAdd(&g_gsum[2 * tid],     sAcc[3 * tid + 0]);
        atomicAdd(&g_gsum[2 * tid + 1], sAcc[3 * tid + 1]);
        atomicAdd(&g_gcnt[tid],         sAcc[3 * tid + 2]);
        __threadfence();
    }
    __syncthreads();
    if (tid == 0) {
        int old = atomicAdd(&g_done, 1);
        sLast = (old == PQC_BLOCKS - 1);
        __threadfence();
    }
    __syncthreads();

    if (sLast && tid < NUM_GRAPHS) {
        int g = tid;
        float cnt = __ldcg(&g_gcnt[g]);
        float g0 = __ldcg(&g_gsum[2 * g]) / cnt;
        float g1 = __ldcg(&g_gsum[2 * g + 1]) / cnt;
        float h0 = g0 * Wh1[0] + g1 * Wh1[2] + bh1[0];
        float h1 = g0 * Wh1[1] + g1 * Wh1[3] + bh1[1];
        h0 = h0 > 0.f ? h0 : 0.01f * h0;
        h1 = h1 > 0.f ? h1 : 0.01f * h1;
        out[2 * g]     = h0 * Wh2[0] + h1 * Wh2[2] + bh2[0];
        out[2 * g + 1] = h0 * Wh2[1] + h1 * Wh2[3] + bh2[1];
    }
}

// ---------------- launch ----------------
extern "C" void kernel_launch(void* const* d_in, const int* in_sizes, int n_in,
                              void* d_out, int out_size) {
    const float* node_feat = (const float*)d_in[0];
    const float* edge_attr = (const float*)d_in[1];
    const float* Wn1 = (const float*)d_in[2];
    const float* bn1 = (const float*)d_in[3];
    const float* Wn2 = (const float*)d_in[4];
    const float* bn2 = (const float*)d_in[5];
    const float* We1 = (const float*)d_in[6];
    const float* be1 = (const float*)d_in[7];
    const float* We2 = (const float*)d_in[8];
    const float* be2 = (const float*)d_in[9];
    const float* strong = (const float*)d_in[10];
    const float* inits  = (const float*)d_in[11];
    const float* update = (const float*)d_in[12];
    const float* Wu1 = (const float*)d_in[13];
    const float* bu1 = (const float*)d_in[14];
    const float* Wu2 = (const float*)d_in[15];
    const float* bu2 = (const float*)d_in[16];
    const float* Wh1 = (const float*)d_in[17];
    const float* bh1 = (const float*)d_in[18];
    const float* Wh2 = (const float*)d_in[19];
    const float* bh2 = (const float*)d_in[20];
    const int* subgraphs = (const int*)d_in[21];
    const int* edge_ids  = (const int*)d_in[22];
    const int* batch     = (const int*)d_in[23];
    float* out = (float*)d_out;

    mlp_fused_kernel<<<128, 128>>>(node_feat, Wn1, bn1, Wn2, bn2,
                                   edge_attr, We1, be1, We2, be2,
                                   strong, inits, update);
    pqc_kernel<<<PQC_BLOCKS, 256>>>(subgraphs, edge_ids, batch,
                                    Wu1, bu1, Wu2, bu2,
                                    Wh1, bh1, Wh2, bh2, out);
}